// round 11
// baseline (speedup 1.0000x reference)
#include <cuda_runtime.h>
#include <math.h>

// ---------------- problem constants ----------------
#define B_    2
#define C_    48
#define T_    16
#define H_    64
#define W_    64
#define N_    65536          // T*H*W per batch
#define HEADS_ 4
#define NSPLIT 128

typedef unsigned long long u64;

// ---------------- f32x2 packed helpers ----------------
__device__ __forceinline__ u64 pack2(float lo, float hi) {
    u64 r; asm("mov.b64 %0,{%1,%2};" : "=l"(r) : "f"(lo), "f"(hi)); return r;
}
__device__ __forceinline__ void unpack2(u64 v, float& lo, float& hi) {
    asm("mov.b64 {%0,%1},%2;" : "=f"(lo), "=f"(hi) : "l"(v));
}
__device__ __forceinline__ u64 fma2(u64 a, u64 b, u64 c) {
    u64 d; asm("fma.rn.f32x2 %0,%1,%2,%3;" : "=l"(d) : "l"(a), "l"(b), "l"(c)); return d;
}

// ---------------- scratch (static device globals; no allocs) ----------------
__device__ float g_qkv [(size_t)B_*576*N_];
__device__ float g_qkv2[(size_t)B_*576*N_];
__device__ float g_t192[(size_t)B_*192*N_];
__device__ float g_ln  [(size_t)B_*C_*N_];
__device__ float g_part[(size_t)NSPLIT*B_*HEADS_*48*48];
__device__ float g_attn[(size_t)B_*HEADS_*48*48];
__device__ float g_M   [(size_t)B_*192*48];     // proj_w @ attn, [b][hd][co]
__device__ float g_sumsq[(size_t)B_*384];

// ---------------- zero kernel (sumsq init + profiling slot alignment) ----------
__global__ void zero_kernel(float* __restrict__ p, int n) {
    int i = blockIdx.x * blockDim.x + threadIdx.x;
    if (i < n) p[i] = 0.f;
}

// ---------------- LayerNorm over channel dim ----------------
__global__ void ln_kernel(const float* __restrict__ x, const float* __restrict__ w,
                          const float* __restrict__ b, float* __restrict__ y) {
    int idx = blockIdx.x * blockDim.x + threadIdx.x;
    if (idx >= B_ * N_) return;
    int bi = idx / N_, n = idx - bi * N_;
    const float* xp = x + (size_t)bi * C_ * N_ + n;
    float v[C_];
    float mu = 0.f;
#pragma unroll
    for (int c = 0; c < C_; c++) { v[c] = xp[(size_t)c * N_]; mu += v[c]; }
    mu *= (1.f / C_);
    float var = 0.f;
#pragma unroll
    for (int c = 0; c < C_; c++) { float d = v[c] - mu; var += d * d; }
    var *= (1.f / C_);
    float inv = rsqrtf(var + 1e-5f);
    float* yp = y + (size_t)bi * C_ * N_ + n;
#pragma unroll
    for (int c = 0; c < C_; c++) yp[(size_t)c * N_] = (v[c] - mu) * inv * w[c] + b[c];
}

// ---------------- 1x1x1 conv: transposed smem weights, LDS.128, NPT positions -------
template<int CIN, int CO_TILE, int NPT>
__global__ void __launch_bounds__(256) conv1x1_kernel(
        const float* __restrict__ in, const float* __restrict__ wgt,
        const float* __restrict__ bias, const float* __restrict__ res,
        float* __restrict__ out, int cout) {
    __shared__ float ws[CIN][CO_TILE];     // c-major: o contiguous -> LDS.128
    __shared__ float bs[CO_TILE];
    int tid = threadIdx.x;
    int cb = blockIdx.y * CO_TILE;
    int b  = blockIdx.z;
    for (int i = tid; i < CO_TILE * CIN; i += 256) {
        int o = i / CIN, c = i % CIN;
        ws[c][o] = wgt[(size_t)(cb + o) * CIN + c];
    }
    for (int i = tid; i < CO_TILE; i += 256) bs[i] = bias[cb + i];
    __syncthreads();
    int n0 = (blockIdx.x * 256 + tid) * NPT;
    float acc[CO_TILE][NPT];
#pragma unroll
    for (int o = 0; o < CO_TILE; o++)
#pragma unroll
        for (int p = 0; p < NPT; p++) acc[o][p] = bs[o];
    const float* ip = in + (size_t)b * CIN * N_ + n0;
#pragma unroll 4
    for (int c = 0; c < CIN; c++) {
        float xv[NPT];
        if (NPT == 2) {
            float2 x2 = *reinterpret_cast<const float2*>(ip + (size_t)c * N_);
            xv[0] = x2.x; xv[1] = x2.y;
        } else {
            xv[0] = ip[(size_t)c * N_];
        }
        const float4* wr = reinterpret_cast<const float4*>(&ws[c][0]);
#pragma unroll
        for (int o4 = 0; o4 < CO_TILE / 4; o4++) {
            float4 wv = wr[o4];
#pragma unroll
            for (int p = 0; p < NPT; p++) {
                acc[o4 * 4 + 0][p] = fmaf(wv.x, xv[p], acc[o4 * 4 + 0][p]);
                acc[o4 * 4 + 1][p] = fmaf(wv.y, xv[p], acc[o4 * 4 + 1][p]);
                acc[o4 * 4 + 2][p] = fmaf(wv.z, xv[p], acc[o4 * 4 + 2][p]);
                acc[o4 * 4 + 3][p] = fmaf(wv.w, xv[p], acc[o4 * 4 + 3][p]);
            }
        }
    }
    float* op = out + ((size_t)b * cout + cb) * N_ + n0;
    if (res) {
        const float* rp = res + ((size_t)b * cout + cb) * N_ + n0;
#pragma unroll
        for (int o = 0; o < CO_TILE; o++) {
            if (NPT == 2) {
                float2 rv = *reinterpret_cast<const float2*>(rp + (size_t)o * N_);
                *reinterpret_cast<float2*>(op + (size_t)o * N_) =
                    make_float2(acc[o][0] + rv.x, acc[o][1] + rv.y);
            } else {
                op[(size_t)o * N_] = acc[o][0] + rp[(size_t)o * N_];
            }
        }
    } else {
#pragma unroll
        for (int o = 0; o < CO_TILE; o++) {
            if (NPT == 2) {
                *reinterpret_cast<float2*>(op + (size_t)o * N_) =
                    make_float2(acc[o][0], acc[o][1]);
            } else {
                op[(size_t)o * N_] = acc[o][0];
            }
        }
    }
}

// ---------------- grouped 3x3x3 conv (576ch): f32x2, kh-outer, whole group/thread -----
// block = (b, g, t, h-quarter), 128 thr; each thread: 2h x 4w (as 2 ow-pairs) x 4 oc.
// Weights staged in smem as DUPLICATED float2 pairs, layout [ci][kd][kh][oc][j].
// Fused: sum-of-squares for q/k channels.
__global__ void __launch_bounds__(128) gdw576_kernel(
        const float* __restrict__ in, const float* __restrict__ wgt,
        const float* __restrict__ bias, float* __restrict__ out,
        float* __restrict__ sumsq) {
    __shared__ float2 ws2[432];            // [ci][kd][kh][oc*3+j], duplicated pairs
    int tid = threadIdx.x;
    int bidx = blockIdx.x;                 // B * 144 * 16 * 4
    int hquart = bidx & 3;
    int t = (bidx >> 2) & 15;
    int g = (bidx >> 6) % 144;
    int b = bidx / (64 * 144);

    for (int i = tid; i < 432; i += 128) {
        int ci = i / 108, rem = i % 108;
        int kd = rem / 36, r2 = rem % 36;
        int oc = r2 / 9,  jj = r2 % 9;
        int kh = jj / 3,  j  = jj % 3;
        float wv = wgt[(size_t)((g * 4 + oc) * 4 + ci) * 27 + kd * 9 + jj];
        ws2[((ci * 3 + kd) * 3 + kh) * 12 + oc * 3 + j] = make_float2(wv, wv);
    }
    __syncthreads();

    int wq = tid & 15, hq = tid >> 4;      // hq 0..7
    int w0 = wq * 4;
    int h0 = hquart * 16 + hq * 2;

    u64 acc[4][2][2];                      // [oc][oh][ow-pair]
#pragma unroll
    for (int oc = 0; oc < 4; oc++) {
        float bv = bias[g * 4 + oc];
        u64 bp = pack2(bv, bv);
#pragma unroll
        for (int i = 0; i < 2; i++) { acc[oc][i][0] = bp; acc[oc][i][1] = bp; }
    }

#pragma unroll
    for (int ci = 0; ci < 4; ci++) {
        const float* ip = in + (size_t)(b * 576 + g * 4 + ci) * (T_ * H_ * W_);
#pragma unroll
        for (int kd = 0; kd < 3; kd++) {
            int tt = t + kd - 1;
            if ((unsigned)tt >= (unsigned)T_) continue;   // uniform per block
            const float* pl = ip + (size_t)tt * H_ * W_;
#pragma unroll
            for (int kh = 0; kh < 3; kh++) {
                u64 wk2[12];
                {
                    const ulonglong2* wp = reinterpret_cast<const ulonglong2*>(
                        &ws2[((ci * 3 + kd) * 3 + kh) * 12]);
#pragma unroll
                    for (int j6 = 0; j6 < 6; j6++) {
                        ulonglong2 v2 = wp[j6];
                        wk2[2 * j6] = v2.x; wk2[2 * j6 + 1] = v2.y;
                    }
                }
#pragma unroll
                for (int oh = 0; oh < 2; oh++) {
                    int rr = kh + oh;                     // input row index 0..3
                    int hh = h0 - 1 + rr;
                    float4 m = make_float4(0.f, 0.f, 0.f, 0.f);
                    if ((unsigned)hh < (unsigned)H_)
                        m = *reinterpret_cast<const float4*>(pl + hh * W_ + w0);
                    float e0 = __shfl_up_sync(0xffffffffu, m.w, 1);
                    float e5 = __shfl_down_sync(0xffffffffu, m.x, 1);
                    if (wq == 0)  e0 = 0.f;
                    if (wq == 15) e5 = 0.f;
                    u64 p0 = pack2(e0,  m.x);
                    u64 p1 = pack2(m.x, m.y);
                    u64 p2 = pack2(m.y, m.z);
                    u64 p3 = pack2(m.z, m.w);
                    u64 p4 = pack2(m.w, e5);
#pragma unroll
                    for (int oc = 0; oc < 4; oc++) {
                        u64 k0 = wk2[oc * 3 + 0];
                        u64 k1 = wk2[oc * 3 + 1];
                        u64 k2 = wk2[oc * 3 + 2];
                        acc[oc][oh][0] = fma2(k0, p0,
                                          fma2(k1, p1,
                                           fma2(k2, p2, acc[oc][oh][0])));
                        acc[oc][oh][1] = fma2(k0, p2,
                                          fma2(k1, p3,
                                           fma2(k2, p4, acc[oc][oh][1])));
                    }
                }
            }
        }
    }

    float ssq[4] = {0.f, 0.f, 0.f, 0.f};
#pragma unroll
    for (int oc = 0; oc < 4; oc++) {
        float* opd = out + ((size_t)(b * 576 + g * 4 + oc) * T_ + t) * H_ * W_;
#pragma unroll
        for (int oh = 0; oh < 2; oh++) {
            float v0, v1, v2, v3;
            unpack2(acc[oc][oh][0], v0, v1);
            unpack2(acc[oc][oh][1], v2, v3);
            *reinterpret_cast<float4*>(opd + (h0 + oh) * W_ + w0) = make_float4(v0, v1, v2, v3);
            ssq[oc] += v0 * v0 + v1 * v1 + v2 * v2 + v3 * v3;
        }
    }
    if (g < 96) {   // q/k channels only
#pragma unroll
        for (int oc = 0; oc < 4; oc++) {
#pragma unroll
            for (int off = 16; off; off >>= 1)
                ssq[oc] += __shfl_down_sync(0xffffffffu, ssq[oc], off);
        }
        if ((tid & 31) == 0) {
#pragma unroll
            for (int oc = 0; oc < 4; oc++)
                atomicAdd(&sumsq[b * 384 + g * 4 + oc], ssq[oc]);
        }
    }
}

// ---------------- FFN depthwise 3x3x3 + GELU gate fused ----------------
__global__ void __launch_bounds__(256) ffn_dw_gate_kernel(
        const float* __restrict__ in,   // 192 channels
        const float* __restrict__ wgt, const float* __restrict__ bias,
        float* __restrict__ out) {      // 96 channels (gated)
    long idx = (long)blockIdx.x * 256 + threadIdx.x;
    int wq = (int)(idx & 15);
    long rest = idx >> 4;
    int hq = (int)(rest & 15); rest >>= 4;
    int t  = (int)(rest & 15); rest >>= 4;
    int c  = (int)(rest % 96);
    int b  = (int)(rest / 96);
    int w0 = wq * 4, h0 = hq * 4;

    float acc[2][4][4];
    {
        float b1 = bias[c], b2 = bias[c + 96];
#pragma unroll
        for (int i = 0; i < 4; i++)
#pragma unroll
            for (int j = 0; j < 4; j++) { acc[0][i][j] = b1; acc[1][i][j] = b2; }
    }

#pragma unroll
    for (int s = 0; s < 2; s++) {
        int ch = c + 96 * s;
        const float* wb = wgt + (size_t)ch * 27;
        const float* ip = in + (size_t)(b * 192 + ch) * (T_ * H_ * W_);
#pragma unroll
        for (int kd = 0; kd < 3; kd++) {
            int tt = t + kd - 1;
            if ((unsigned)tt >= (unsigned)T_) continue;
            float wk[9];
#pragma unroll
            for (int j = 0; j < 9; j++) wk[j] = wb[kd * 9 + j];
            const float* pl = ip + (size_t)tt * H_ * W_;
#pragma unroll
            for (int r = 0; r < 6; r++) {
                int hh = h0 - 1 + r;
                float4 m = make_float4(0.f, 0.f, 0.f, 0.f);
                if ((unsigned)hh < (unsigned)H_)
                    m = *reinterpret_cast<const float4*>(pl + hh * W_ + w0);
                float e0 = __shfl_up_sync(0xffffffffu, m.w, 1);
                float e5 = __shfl_down_sync(0xffffffffu, m.x, 1);
                if (wq == 0)  e0 = 0.f;
                if (wq == 15) e5 = 0.f;
                float v[6] = { e0, m.x, m.y, m.z, m.w, e5 };
#pragma unroll
                for (int kh = 0; kh < 3; kh++) {
                    int oh = r - kh;
                    if (oh < 0 || oh > 3) continue;
                    float k0 = wk[kh * 3 + 0], k1 = wk[kh * 3 + 1], k2 = wk[kh * 3 + 2];
#pragma unroll
                    for (int ow = 0; ow < 4; ow++)
                        acc[s][oh][ow] = fmaf(k0, v[ow],
                                          fmaf(k1, v[ow + 1],
                                           fmaf(k2, v[ow + 2], acc[s][oh][ow])));
                }
            }
        }
    }

    float* opd = out + ((size_t)(b * 96 + c) * T_ + t) * H_ * W_;
#pragma unroll
    for (int oh = 0; oh < 4; oh++) {
        float gv[4];
#pragma unroll
        for (int ow = 0; ow < 4; ow++) {
            float a = acc[0][oh][ow];
            gv[ow] = 0.5f * a * (1.f + erff(a * 0.70710678118654752f)) * acc[1][oh][ow];
        }
        *reinterpret_cast<float4*>(opd + (h0 + oh) * W_ + w0) =
            make_float4(gv[0], gv[1], gv[2], gv[3]);
    }
}

// ---------------- q·k^T partials: 512-slice, reg-prefetch pipeline ----------------
__global__ void __launch_bounds__(256) qk_kernel(const float* __restrict__ qkv2,
                                                 float* __restrict__ part) {
    __shared__ float qs[48][36];
    __shared__ float ks[48][36];
    int ns = blockIdx.x, h = blockIdx.y, b = blockIdx.z;
    int tid = threadIdx.x;
    int tx = tid & 15, ty = tid >> 4;
    int c0 = tx * 3, d0 = ty * 3;
    const float* qbase = qkv2 + (size_t)(b * 576 + h * 48) * N_;
    const float* kbase = qkv2 + (size_t)(b * 576 + 192 + h * 48) * N_;
    int nbase = ns * (N_ / NSPLIT);

    int iqk[3], ic[3], in4[3];
#pragma unroll
    for (int j = 0; j < 3; j++) {
        int idx = j * 256 + tid;
        iqk[j] = idx / 384;
        int rem = idx % 384;
        ic[j] = rem >> 3;
        in4[j] = rem & 7;
    }
    float acc[3][3] = {};
    float4 rbuf[3], rnext[3];
#pragma unroll
    for (int j = 0; j < 3; j++) {
        const float* base = iqk[j] ? kbase : qbase;
        rbuf[j] = *reinterpret_cast<const float4*>(base + (size_t)ic[j] * N_ + nbase + in4[j] * 4);
        rnext[j] = rbuf[j];
    }

    for (int ch = 0; ch < 16; ch++) {
#pragma unroll
        for (int j = 0; j < 3; j++) {
            float* dst = (iqk[j] ? &ks[0][0] : &qs[0][0]) + ic[j] * 36 + in4[j] * 4;
            *reinterpret_cast<float4*>(dst) = rbuf[j];
        }
        __syncthreads();
        if (ch < 15) {
            int off = (ch + 1) * 32;
#pragma unroll
            for (int j = 0; j < 3; j++) {
                const float* base = iqk[j] ? kbase : qbase;
                rnext[j] = *reinterpret_cast<const float4*>(
                    base + (size_t)ic[j] * N_ + nbase + off + in4[j] * 4);
            }
        }
#pragma unroll
        for (int nn = 0; nn < 32; nn += 2) {
            float2 q0 = *reinterpret_cast<const float2*>(&qs[c0 + 0][nn]);
            float2 q1 = *reinterpret_cast<const float2*>(&qs[c0 + 1][nn]);
            float2 q2 = *reinterpret_cast<const float2*>(&qs[c0 + 2][nn]);
            float2 k0 = *reinterpret_cast<const float2*>(&ks[d0 + 0][nn]);
            float2 k1 = *reinterpret_cast<const float2*>(&ks[d0 + 1][nn]);
            float2 k2 = *reinterpret_cast<const float2*>(&ks[d0 + 2][nn]);
            acc[0][0] = fmaf(q0.x, k0.x, fmaf(q0.y, k0.y, acc[0][0]));
            acc[0][1] = fmaf(q0.x, k1.x, fmaf(q0.y, k1.y, acc[0][1]));
            acc[0][2] = fmaf(q0.x, k2.x, fmaf(q0.y, k2.y, acc[0][2]));
            acc[1][0] = fmaf(q1.x, k0.x, fmaf(q1.y, k0.y, acc[1][0]));
            acc[1][1] = fmaf(q1.x, k1.x, fmaf(q1.y, k1.y, acc[1][1]));
            acc[1][2] = fmaf(q1.x, k2.x, fmaf(q1.y, k2.y, acc[1][2]));
            acc[2][0] = fmaf(q2.x, k0.x, fmaf(q2.y, k0.y, acc[2][0]));
            acc[2][1] = fmaf(q2.x, k1.x, fmaf(q2.y, k1.y, acc[2][1]));
            acc[2][2] = fmaf(q2.x, k2.x, fmaf(q2.y, k2.y, acc[2][2]));
        }
        __syncthreads();
#pragma unroll
        for (int j = 0; j < 3; j++) rbuf[j] = rnext[j];
    }

    float* pp = part + (((size_t)ns * B_ + b) * HEADS_ + h) * 2304;
#pragma unroll
    for (int i = 0; i < 3; i++)
#pragma unroll
        for (int j = 0; j < 3; j++) pp[(c0 + i) * 48 + d0 + j] = acc[i][j];
}

// ---------------- reduce partials, scale by rsqrt(sumsq) & temperature, softmax ----------
__global__ void softmax_kernel(const float* __restrict__ part, const float* __restrict__ sumsq,
                               const float* __restrict__ temp, float* __restrict__ attn) {
    int c = blockIdx.x, h = blockIdx.y, b = blockIdx.z;
    int d = threadIdx.x;
    __shared__ float sv[48];
    __shared__ float m_s, sum_s;
    float s = 0.f;
    if (d < 48) {
        const float* pp = part + ((size_t)b * HEADS_ + h) * 2304 + c * 48 + d;
        const size_t stride = (size_t)B_ * HEADS_ * 2304;
        for (int p = 0; p < NSPLIT; p++) s += pp[(size_t)p * stride];
        float rq = 1.f / fmaxf(sqrtf(sumsq[b * 384 + h * 48 + c]), 1e-12f);
        float rk = 1.f / fmaxf(sqrtf(sumsq[b * 384 + 192 + h * 48 + d]), 1e-12f);
        s *= rq * rk * temp[h];
        sv[d] = s;
    }
    __syncthreads();
    if (threadIdx.x == 0) {
        float m = sv[0];
        for (int i = 1; i < 48; i++) m = fmaxf(m, sv[i]);
        m_s = m;
    }
    __syncthreads();
    float e = 0.f;
    if (d < 48) { e = expf(s - m_s); sv[d] = e; }
    __syncthreads();
    if (threadIdx.x == 0) {
        float t2 = 0.f;
        for (int i = 0; i < 48; i++) t2 += sv[i];
        sum_s = t2;
    }
    __syncthreads();
    if (d < 48) attn[(((size_t)b * HEADS_ + h) * 48 + c) * 48 + d] = e / sum_s;
}

// ---------------- M = proj_w @ attn  (per batch; [hd][co] layout) ----------------
__global__ void mm_kernel(const float* __restrict__ proj_w, const float* __restrict__ attn,
                          float* __restrict__ M) {
    __shared__ float at[48][48];   // [c][d]
    __shared__ float pw[48][48];   // [co][c]
    int h = blockIdx.x, b = blockIdx.y;
    int tid = threadIdx.x;
    for (int i = tid; i < 2304; i += 256) {
        int c = i / 48, d = i % 48;
        at[c][d] = attn[((size_t)b * HEADS_ + h) * 2304 + i];
        int co = i / 48, cc = i % 48;
        pw[co][cc] = proj_w[(size_t)co * 192 + h * 48 + cc];
    }
    __syncthreads();
    for (int i = tid; i < 2304; i += 256) {
        int co = i / 48, d = i % 48;
        float s = 0.f;
#pragma unroll 8
        for (int c = 0; c < 48; c++) s = fmaf(pw[co][c], at[c][d], s);
        M[((size_t)b * 192 + h * 48 + d) * 48 + co] = s;
    }
}

// ---------------- out = M @ v + proj_b + x  (fused attn·v + proj + residual) ----------
__global__ void __launch_bounds__(256) avproj_kernel(
        const float* __restrict__ qkv2, const float* __restrict__ M,
        const float* __restrict__ bias, const float* __restrict__ x,
        float* __restrict__ out) {
    __shared__ float Ms[192][48];          // [hd][co]
    int b = blockIdx.y;
    int tid = threadIdx.x;
    for (int i = tid; i < 192 * 48; i += 256)
        (&Ms[0][0])[i] = M[(size_t)b * 192 * 48 + i];
    __syncthreads();
    int n = blockIdx.x * 256 + tid;
    const float* vb = qkv2 + (size_t)(b * 576 + 384) * N_ + n;
    float acc[48];
#pragma unroll
    for (int co = 0; co < 48; co++) acc[co] = bias[co];
#pragma unroll 4
    for (int hd = 0; hd < 192; hd++) {
        float v = vb[(size_t)hd * N_];
        const float4* mr = reinterpret_cast<const float4*>(&Ms[hd][0]);
#pragma unroll
        for (int c4 = 0; c4 < 12; c4++) {
            float4 a = mr[c4];
            acc[c4 * 4 + 0] = fmaf(a.x, v, acc[c4 * 4 + 0]);
            acc[c4 * 4 + 1] = fmaf(a.y, v, acc[c4 * 4 + 1]);
            acc[c4 * 4 + 2] = fmaf(a.z, v, acc[c4 * 4 + 2]);
            acc[c4 * 4 + 3] = fmaf(a.w, v, acc[c4 * 4 + 3]);
        }
    }
    const float* xp = x + (size_t)b * 48 * N_ + n;
    float* op = out + (size_t)b * 48 * N_ + n;
#pragma unroll
    for (int co = 0; co < 48; co++) op[(size_t)co * N_] = acc[co] + xp[(size_t)co * N_];
}

// ---------------- launcher ----------------
extern "C" void kernel_launch(void* const* d_in, const int* in_sizes, int n_in,
                              void* d_out, int out_size) {
    (void)in_sizes; (void)n_in; (void)out_size;
    const float* x      = (const float*)d_in[0];
    const float* ln1_w  = (const float*)d_in[1];
    const float* ln1_b  = (const float*)d_in[2];
    const float* qkv_w  = (const float*)d_in[3];
    const float* qkv_b  = (const float*)d_in[4];
    const float* qkvdw_w= (const float*)d_in[5];
    const float* qkvdw_b= (const float*)d_in[6];
    const float* temper = (const float*)d_in[7];
    const float* proj_w = (const float*)d_in[8];
    const float* proj_b = (const float*)d_in[9];
    const float* ln2_w  = (const float*)d_in[10];
    const float* ln2_b  = (const float*)d_in[11];
    const float* pin_w  = (const float*)d_in[12];
    const float* pin_b  = (const float*)d_in[13];
    const float* dw_w   = (const float*)d_in[14];
    const float* dw_b   = (const float*)d_in[15];
    const float* pout_w = (const float*)d_in[16];
    const float* pout_b = (const float*)d_in[17];
    float* out = (float*)d_out;

    float *qkv, *qkv2, *t192, *ln, *part, *attn, *Mbuf, *sumsq;
    cudaGetSymbolAddress((void**)&qkv,  g_qkv);
    cudaGetSymbolAddress((void**)&qkv2, g_qkv2);
    cudaGetSymbolAddress((void**)&t192, g_t192);
    cudaGetSymbolAddress((void**)&ln,   g_ln);
    cudaGetSymbolAddress((void**)&part, g_part);
    cudaGetSymbolAddress((void**)&attn, g_attn);
    cudaGetSymbolAddress((void**)&Mbuf, g_M);
    cudaGetSymbolAddress((void**)&sumsq,g_sumsq);

    // launch 0: zero sumsq (gdw576 lands at the profiled 4th launch)
    zero_kernel<<<3, 256>>>(sumsq, B_ * 384);                                                   // 0

    // ---- attention branch ----
    ln_kernel<<<(B_ * N_) / 256, 256>>>(x, ln1_w, ln1_b, ln);                                   // 1

    conv1x1_kernel<48, 16, 2><<<dim3(N_ / 512, 576 / 16, B_), 256>>>(ln, qkv_w, qkv_b, nullptr, qkv, 576); // 2

    gdw576_kernel<<<B_ * 144 * T_ * 4, 128>>>(qkv, qkvdw_w, qkvdw_b, qkv2, sumsq);              // 3 <- profiled

    qk_kernel<<<dim3(NSPLIT, HEADS_, B_), 256>>>(qkv2, part);                                   // 4

    softmax_kernel<<<dim3(48, HEADS_, B_), 64>>>(part, sumsq, temper, attn);                    // 5

    mm_kernel<<<dim3(HEADS_, B_), 256>>>(proj_w, attn, Mbuf);                                   // 6

    avproj_kernel<<<dim3(N_ / 256, B_), 256>>>(qkv2, Mbuf, proj_b, x, out);                     // 7

    // ---- FFN branch ----
    ln_kernel<<<(B_ * N_) / 256, 256>>>(out, ln2_w, ln2_b, ln);                                 // 8

    conv1x1_kernel<48, 16, 2><<<dim3(N_ / 512, 192 / 16, B_), 256>>>(ln, pin_w, pin_b, nullptr, t192, 192); // 9

    ffn_dw_gate_kernel<<<(B_ * 96 * T_ * 16 * 16) / 256, 256>>>(t192, dw_w, dw_b, qkv);         // 10

    conv1x1_kernel<96, 48, 1><<<dim3(N_ / 256, 1, B_), 256>>>(qkv, pout_w, pout_b, out, out, 48); // 11
}

// round 12
// speedup vs baseline: 1.0793x; 1.0793x over previous
#include <cuda_runtime.h>
#include <math.h>

// ---------------- problem constants ----------------
#define B_    2
#define C_    48
#define T_    16
#define H_    64
#define W_    64
#define N_    65536          // T*H*W per batch
#define HEADS_ 4
#define NSPLIT 256

// ---------------- scratch (static device globals; no allocs) ----------------
__device__ float g_qkv [(size_t)B_*576*N_];
__device__ float g_qkv2[(size_t)B_*576*N_];
__device__ float g_t192[(size_t)B_*192*N_];
__device__ float g_ln  [(size_t)B_*C_*N_];
__device__ float g_part[(size_t)NSPLIT*B_*HEADS_*48*48];
__device__ float g_attn[(size_t)B_*HEADS_*48*48];
__device__ float g_M   [(size_t)B_*192*48];     // proj_w @ attn, [b][hd][co]
__device__ float g_sumsq[(size_t)B_*384];

// ---------------- zero kernel (sumsq init + profiling slot alignment) ----------
__global__ void zero_kernel(float* __restrict__ p, int n) {
    int i = blockIdx.x * blockDim.x + threadIdx.x;
    if (i < n) p[i] = 0.f;
}

// ---------------- LayerNorm over channel dim ----------------
__global__ void ln_kernel(const float* __restrict__ x, const float* __restrict__ w,
                          const float* __restrict__ b, float* __restrict__ y) {
    int idx = blockIdx.x * blockDim.x + threadIdx.x;
    if (idx >= B_ * N_) return;
    int bi = idx / N_, n = idx - bi * N_;
    const float* xp = x + (size_t)bi * C_ * N_ + n;
    float v[C_];
    float mu = 0.f;
#pragma unroll
    for (int c = 0; c < C_; c++) { v[c] = xp[(size_t)c * N_]; mu += v[c]; }
    mu *= (1.f / C_);
    float var = 0.f;
#pragma unroll
    for (int c = 0; c < C_; c++) { float d = v[c] - mu; var += d * d; }
    var *= (1.f / C_);
    float inv = rsqrtf(var + 1e-5f);
    float* yp = y + (size_t)bi * C_ * N_ + n;
#pragma unroll
    for (int c = 0; c < C_; c++) yp[(size_t)c * N_] = (v[c] - mu) * inv * w[c] + b[c];
}

// ---------------- 1x1x1 conv: transposed smem weights, LDS.128, NPT positions -------
template<int CIN, int CO_TILE, int NPT>
__global__ void __launch_bounds__(256) conv1x1_kernel(
        const float* __restrict__ in, const float* __restrict__ wgt,
        const float* __restrict__ bias, const float* __restrict__ res,
        float* __restrict__ out, int cout) {
    __shared__ float ws[CIN][CO_TILE];     // c-major: o contiguous -> LDS.128
    __shared__ float bs[CO_TILE];
    int tid = threadIdx.x;
    int cb = blockIdx.y * CO_TILE;
    int b  = blockIdx.z;
    for (int i = tid; i < CO_TILE * CIN; i += 256) {
        int o = i / CIN, c = i % CIN;
        ws[c][o] = wgt[(size_t)(cb + o) * CIN + c];
    }
    for (int i = tid; i < CO_TILE; i += 256) bs[i] = bias[cb + i];
    __syncthreads();
    int n0 = (blockIdx.x * 256 + tid) * NPT;
    float acc[CO_TILE][NPT];
#pragma unroll
    for (int o = 0; o < CO_TILE; o++)
#pragma unroll
        for (int p = 0; p < NPT; p++) acc[o][p] = bs[o];
    const float* ip = in + (size_t)b * CIN * N_ + n0;
#pragma unroll 4
    for (int c = 0; c < CIN; c++) {
        float xv[NPT];
        if (NPT == 2) {
            float2 x2 = *reinterpret_cast<const float2*>(ip + (size_t)c * N_);
            xv[0] = x2.x; xv[1] = x2.y;
        } else {
            xv[0] = ip[(size_t)c * N_];
        }
        const float4* wr = reinterpret_cast<const float4*>(&ws[c][0]);
#pragma unroll
        for (int o4 = 0; o4 < CO_TILE / 4; o4++) {
            float4 wv = wr[o4];
#pragma unroll
            for (int p = 0; p < NPT; p++) {
                acc[o4 * 4 + 0][p] = fmaf(wv.x, xv[p], acc[o4 * 4 + 0][p]);
                acc[o4 * 4 + 1][p] = fmaf(wv.y, xv[p], acc[o4 * 4 + 1][p]);
                acc[o4 * 4 + 2][p] = fmaf(wv.z, xv[p], acc[o4 * 4 + 2][p]);
                acc[o4 * 4 + 3][p] = fmaf(wv.w, xv[p], acc[o4 * 4 + 3][p]);
            }
        }
    }
    float* op = out + ((size_t)b * cout + cb) * N_ + n0;
    if (res) {
        const float* rp = res + ((size_t)b * cout + cb) * N_ + n0;
#pragma unroll
        for (int o = 0; o < CO_TILE; o++) {
            if (NPT == 2) {
                float2 rv = *reinterpret_cast<const float2*>(rp + (size_t)o * N_);
                *reinterpret_cast<float2*>(op + (size_t)o * N_) =
                    make_float2(acc[o][0] + rv.x, acc[o][1] + rv.y);
            } else {
                op[(size_t)o * N_] = acc[o][0] + rp[(size_t)o * N_];
            }
        }
    } else {
#pragma unroll
        for (int o = 0; o < CO_TILE; o++) {
            if (NPT == 2) {
                *reinterpret_cast<float2*>(op + (size_t)o * N_) =
                    make_float2(acc[o][0], acc[o][1]);
            } else {
                op[(size_t)o * N_] = acc[o][0];
            }
        }
    }
}

// ---------------- grouped 3x3x3 conv (576ch): whole group per thread [r7 scalar body] ---
// block = (b, g, t, h-quarter); each thread: 2h x 4w tile for the group's 4 output ch.
// __launch_bounds__(128, 6): cap regs at 85 to fit 6 blocks/SM (occ 30 -> ~37%).
__global__ void __launch_bounds__(128, 6) gdw576_kernel(
        const float* __restrict__ in, const float* __restrict__ wgt,
        const float* __restrict__ bias, float* __restrict__ out,
        float* __restrict__ sumsq) {
    __shared__ float ws[4 * 3 * 36];       // [ci][kd][oc*9+j]
    int tid = threadIdx.x;
    int bidx = blockIdx.x;                 // B * 144 * 16 * 4
    int hquart = bidx & 3;
    int t = (bidx >> 2) & 15;
    int g = (bidx >> 6) % 144;
    int b = bidx / (64 * 144);

    for (int i = tid; i < 432; i += 128) {
        int ci = i / 108, rem = i % 108;
        int kd = rem / 36, r2 = rem % 36;
        int oc = r2 / 9,  jj = r2 % 9;
        ws[i] = wgt[(size_t)((g * 4 + oc) * 4 + ci) * 27 + kd * 9 + jj];
    }
    __syncthreads();

    int wq = tid & 15, hq = tid >> 4;      // hq 0..7
    int w0 = wq * 4;
    int h0 = hquart * 16 + hq * 2;

    float acc[4][2][4];
#pragma unroll
    for (int oc = 0; oc < 4; oc++) {
        float bv = bias[g * 4 + oc];
#pragma unroll
        for (int i = 0; i < 2; i++)
#pragma unroll
            for (int j = 0; j < 4; j++) acc[oc][i][j] = bv;
    }

#pragma unroll
    for (int ci = 0; ci < 4; ci++) {
        const float* ip = in + (size_t)(b * 576 + g * 4 + ci) * (T_ * H_ * W_);
#pragma unroll
        for (int kd = 0; kd < 3; kd++) {
            int tt = t + kd - 1;
            if ((unsigned)tt >= (unsigned)T_) continue;   // uniform per block
            float wk[36];
            {
                const float4* wp4 = reinterpret_cast<const float4*>(&ws[(ci * 3 + kd) * 36]);
#pragma unroll
                for (int j4 = 0; j4 < 9; j4++) {
                    float4 wv = wp4[j4];
                    wk[j4 * 4 + 0] = wv.x; wk[j4 * 4 + 1] = wv.y;
                    wk[j4 * 4 + 2] = wv.z; wk[j4 * 4 + 3] = wv.w;
                }
            }
            const float* pl = ip + (size_t)tt * H_ * W_;
#pragma unroll
            for (int r = 0; r < 4; r++) {
                int hh = h0 - 1 + r;
                float4 m = make_float4(0.f, 0.f, 0.f, 0.f);
                if ((unsigned)hh < (unsigned)H_)
                    m = *reinterpret_cast<const float4*>(pl + hh * W_ + w0);
                float e0 = __shfl_up_sync(0xffffffffu, m.w, 1);
                float e5 = __shfl_down_sync(0xffffffffu, m.x, 1);
                if (wq == 0)  e0 = 0.f;
                if (wq == 15) e5 = 0.f;
                float v[6] = { e0, m.x, m.y, m.z, m.w, e5 };
#pragma unroll
                for (int kh = 0; kh < 3; kh++) {
                    int oh = r - kh;
                    if (oh < 0 || oh > 1) continue;       // compile-time
#pragma unroll
                    for (int oc = 0; oc < 4; oc++) {
                        float k0 = wk[oc * 9 + kh * 3 + 0];
                        float k1 = wk[oc * 9 + kh * 3 + 1];
                        float k2 = wk[oc * 9 + kh * 3 + 2];
#pragma unroll
                        for (int ow = 0; ow < 4; ow++)
                            acc[oc][oh][ow] = fmaf(k0, v[ow],
                                               fmaf(k1, v[ow + 1],
                                                fmaf(k2, v[ow + 2], acc[oc][oh][ow])));
                    }
                }
            }
        }
    }

    float ssq[4] = {0.f, 0.f, 0.f, 0.f};
#pragma unroll
    for (int oc = 0; oc < 4; oc++) {
        float* opd = out + ((size_t)(b * 576 + g * 4 + oc) * T_ + t) * H_ * W_;
#pragma unroll
        for (int oh = 0; oh < 2; oh++) {
            float v0 = acc[oc][oh][0], v1 = acc[oc][oh][1];
            float v2 = acc[oc][oh][2], v3 = acc[oc][oh][3];
            *reinterpret_cast<float4*>(opd + (h0 + oh) * W_ + w0) = make_float4(v0, v1, v2, v3);
            ssq[oc] += v0 * v0 + v1 * v1 + v2 * v2 + v3 * v3;
        }
    }
    if (g < 96) {   // q/k channels only
#pragma unroll
        for (int oc = 0; oc < 4; oc++) {
#pragma unroll
            for (int off = 16; off; off >>= 1)
                ssq[oc] += __shfl_down_sync(0xffffffffu, ssq[oc], off);
        }
        if ((tid & 31) == 0) {
#pragma unroll
            for (int oc = 0; oc < 4; oc++)
                atomicAdd(&sumsq[b * 384 + g * 4 + oc], ssq[oc]);
        }
    }
}

// ---------------- FFN depthwise 3x3x3 + GELU gate fused ----------------
__global__ void __launch_bounds__(256) ffn_dw_gate_kernel(
        const float* __restrict__ in,   // 192 channels
        const float* __restrict__ wgt, const float* __restrict__ bias,
        float* __restrict__ out) {      // 96 channels (gated)
    long idx = (long)blockIdx.x * 256 + threadIdx.x;
    int wq = (int)(idx & 15);
    long rest = idx >> 4;
    int hq = (int)(rest & 15); rest >>= 4;
    int t  = (int)(rest & 15); rest >>= 4;
    int c  = (int)(rest % 96);
    int b  = (int)(rest / 96);
    int w0 = wq * 4, h0 = hq * 4;

    float acc[2][4][4];
    {
        float b1 = bias[c], b2 = bias[c + 96];
#pragma unroll
        for (int i = 0; i < 4; i++)
#pragma unroll
            for (int j = 0; j < 4; j++) { acc[0][i][j] = b1; acc[1][i][j] = b2; }
    }

#pragma unroll
    for (int s = 0; s < 2; s++) {
        int ch = c + 96 * s;
        const float* wb = wgt + (size_t)ch * 27;
        const float* ip = in + (size_t)(b * 192 + ch) * (T_ * H_ * W_);
#pragma unroll
        for (int kd = 0; kd < 3; kd++) {
            int tt = t + kd - 1;
            if ((unsigned)tt >= (unsigned)T_) continue;
            float wk[9];
#pragma unroll
            for (int j = 0; j < 9; j++) wk[j] = wb[kd * 9 + j];
            const float* pl = ip + (size_t)tt * H_ * W_;
#pragma unroll
            for (int r = 0; r < 6; r++) {
                int hh = h0 - 1 + r;
                float4 m = make_float4(0.f, 0.f, 0.f, 0.f);
                if ((unsigned)hh < (unsigned)H_)
                    m = *reinterpret_cast<const float4*>(pl + hh * W_ + w0);
                float e0 = __shfl_up_sync(0xffffffffu, m.w, 1);
                float e5 = __shfl_down_sync(0xffffffffu, m.x, 1);
                if (wq == 0)  e0 = 0.f;
                if (wq == 15) e5 = 0.f;
                float v[6] = { e0, m.x, m.y, m.z, m.w, e5 };
#pragma unroll
                for (int kh = 0; kh < 3; kh++) {
                    int oh = r - kh;
                    if (oh < 0 || oh > 3) continue;
                    float k0 = wk[kh * 3 + 0], k1 = wk[kh * 3 + 1], k2 = wk[kh * 3 + 2];
#pragma unroll
                    for (int ow = 0; ow < 4; ow++)
                        acc[s][oh][ow] = fmaf(k0, v[ow],
                                          fmaf(k1, v[ow + 1],
                                           fmaf(k2, v[ow + 2], acc[s][oh][ow])));
                }
            }
        }
    }

    float* opd = out + ((size_t)(b * 96 + c) * T_ + t) * H_ * W_;
#pragma unroll
    for (int oh = 0; oh < 4; oh++) {
        float gv[4];
#pragma unroll
        for (int ow = 0; ow < 4; ow++) {
            float a = acc[0][oh][ow];
            gv[ow] = 0.5f * a * (1.f + erff(a * 0.70710678118654752f)) * acc[1][oh][ow];
        }
        *reinterpret_cast<float4*>(opd + (h0 + oh) * W_ + w0) =
            make_float4(gv[0], gv[1], gv[2], gv[3]);
    }
}

// ---------------- q·k^T partials: 256-slice of N, reg-prefetch pipeline ----------------
__global__ void __launch_bounds__(256) qk_kernel(const float* __restrict__ qkv2,
                                                 float* __restrict__ part) {
    __shared__ float qs[48][36];
    __shared__ float ks[48][36];
    int ns = blockIdx.x, h = blockIdx.y, b = blockIdx.z;
    int tid = threadIdx.x;
    int tx = tid & 15, ty = tid >> 4;
    int c0 = tx * 3, d0 = ty * 3;
    const float* qbase = qkv2 + (size_t)(b * 576 + h * 48) * N_;
    const float* kbase = qkv2 + (size_t)(b * 576 + 192 + h * 48) * N_;
    int nbase = ns * (N_ / NSPLIT);          // 256 positions per block

    int iqk[3], ic[3], in4[3];
#pragma unroll
    for (int j = 0; j < 3; j++) {
        int idx = j * 256 + tid;
        iqk[j] = idx / 384;
        int rem = idx % 384;
        ic[j] = rem >> 3;
        in4[j] = rem & 7;
    }
    float acc[3][3] = {};
    float4 rbuf[3], rnext[3];
#pragma unroll
    for (int j = 0; j < 3; j++) {
        const float* base = iqk[j] ? kbase : qbase;
        rbuf[j] = *reinterpret_cast<const float4*>(base + (size_t)ic[j] * N_ + nbase + in4[j] * 4);
        rnext[j] = rbuf[j];
    }

    for (int ch = 0; ch < N_ / NSPLIT / 32; ch++) {   // 8 chunks of 32
#pragma unroll
        for (int j = 0; j < 3; j++) {
            float* dst = (iqk[j] ? &ks[0][0] : &qs[0][0]) + ic[j] * 36 + in4[j] * 4;
            *reinterpret_cast<float4*>(dst) = rbuf[j];
        }
        __syncthreads();
        if (ch < N_ / NSPLIT / 32 - 1) {
            int off = (ch + 1) * 32;
#pragma unroll
            for (int j = 0; j < 3; j++) {
                const float* base = iqk[j] ? kbase : qbase;
                rnext[j] = *reinterpret_cast<const float4*>(
                    base + (size_t)ic[j] * N_ + nbase + off + in4[j] * 4);
            }
        }
#pragma unroll
        for (int nn = 0; nn < 32; nn += 2) {
            float2 q0 = *reinterpret_cast<const float2*>(&qs[c0 + 0][nn]);
            float2 q1 = *reinterpret_cast<const float2*>(&qs[c0 + 1][nn]);
            float2 q2 = *reinterpret_cast<const float2*>(&qs[c0 + 2][nn]);
            float2 k0 = *reinterpret_cast<const float2*>(&ks[d0 + 0][nn]);
            float2 k1 = *reinterpret_cast<const float2*>(&ks[d0 + 1][nn]);
            float2 k2 = *reinterpret_cast<const float2*>(&ks[d0 + 2][nn]);
            acc[0][0] = fmaf(q0.x, k0.x, fmaf(q0.y, k0.y, acc[0][0]));
            acc[0][1] = fmaf(q0.x, k1.x, fmaf(q0.y, k1.y, acc[0][1]));
            acc[0][2] = fmaf(q0.x, k2.x, fmaf(q0.y, k2.y, acc[0][2]));
            acc[1][0] = fmaf(q1.x, k0.x, fmaf(q1.y, k0.y, acc[1][0]));
            acc[1][1] = fmaf(q1.x, k1.x, fmaf(q1.y, k1.y, acc[1][1]));
            acc[1][2] = fmaf(q1.x, k2.x, fmaf(q1.y, k2.y, acc[1][2]));
            acc[2][0] = fmaf(q2.x, k0.x, fmaf(q2.y, k0.y, acc[2][0]));
            acc[2][1] = fmaf(q2.x, k1.x, fmaf(q2.y, k1.y, acc[2][1]));
            acc[2][2] = fmaf(q2.x, k2.x, fmaf(q2.y, k2.y, acc[2][2]));
        }
        __syncthreads();
#pragma unroll
        for (int j = 0; j < 3; j++) rbuf[j] = rnext[j];
    }

    float* pp = part + (((size_t)ns * B_ + b) * HEADS_ + h) * 2304;
#pragma unroll
    for (int i = 0; i < 3; i++)
#pragma unroll
        for (int j = 0; j < 3; j++) pp[(c0 + i) * 48 + d0 + j] = acc[i][j];
}

// ---------------- reduce partials, scale by rsqrt(sumsq) & temperature, softmax ----------
__global__ void softmax_kernel(const float* __restrict__ part, const float* __restrict__ sumsq,
                               const float* __restrict__ temp, float* __restrict__ attn) {
    int c = blockIdx.x, h = blockIdx.y, b = blockIdx.z;
    int d = threadIdx.x;
    __shared__ float sv[48];
    __shared__ float m_s, sum_s;
    float s = 0.f;
    if (d < 48) {
        const float* pp = part + ((size_t)b * HEADS_ + h) * 2304 + c * 48 + d;
        const size_t stride = (size_t)B_ * HEADS_ * 2304;
        for (int p = 0; p < NSPLIT; p++) s += pp[(size_t)p * stride];
        float rq = 1.f / fmaxf(sqrtf(sumsq[b * 384 + h * 48 + c]), 1e-12f);
        float rk = 1.f / fmaxf(sqrtf(sumsq[b * 384 + 192 + h * 48 + d]), 1e-12f);
        s *= rq * rk * temp[h];
        sv[d] = s;
    }
    __syncthreads();
    if (threadIdx.x == 0) {
        float m = sv[0];
        for (int i = 1; i < 48; i++) m = fmaxf(m, sv[i]);
        m_s = m;
    }
    __syncthreads();
    float e = 0.f;
    if (d < 48) { e = expf(s - m_s); sv[d] = e; }
    __syncthreads();
    if (threadIdx.x == 0) {
        float t2 = 0.f;
        for (int i = 0; i < 48; i++) t2 += sv[i];
        sum_s = t2;
    }
    __syncthreads();
    if (d < 48) attn[(((size_t)b * HEADS_ + h) * 48 + c) * 48 + d] = e / sum_s;
}

// ---------------- M = proj_w @ attn  (per batch; [hd][co] layout) ----------------
__global__ void mm_kernel(const float* __restrict__ proj_w, const float* __restrict__ attn,
                          float* __restrict__ M) {
    __shared__ float at[48][48];   // [c][d]
    __shared__ float pw[48][48];   // [co][c]
    int h = blockIdx.x, b = blockIdx.y;
    int tid = threadIdx.x;
    for (int i = tid; i < 2304; i += 256) {
        int c = i / 48, d = i % 48;
        at[c][d] = attn[((size_t)b * HEADS_ + h) * 2304 + i];
        int co = i / 48, cc = i % 48;
        pw[co][cc] = proj_w[(size_t)co * 192 + h * 48 + cc];
    }
    __syncthreads();
    for (int i = tid; i < 2304; i += 256) {
        int co = i / 48, d = i % 48;
        float s = 0.f;
#pragma unroll 8
        for (int c = 0; c < 48; c++) s = fmaf(pw[co][c], at[c][d], s);
        M[((size_t)b * 192 + h * 48 + d) * 48 + co] = s;
    }
}

// ---------------- out = M @ v + proj_b + x  (fused attn·v + proj + residual) ----------
__global__ void __launch_bounds__(256) avproj_kernel(
        const float* __restrict__ qkv2, const float* __restrict__ M,
        const float* __restrict__ bias, const float* __restrict__ x,
        float* __restrict__ out) {
    __shared__ float Ms[192][48];          // [hd][co]
    int b = blockIdx.y;
    int tid = threadIdx.x;
    for (int i = tid; i < 192 * 48; i += 256)
        (&Ms[0][0])[i] = M[(size_t)b * 192 * 48 + i];
    __syncthreads();
    int n = blockIdx.x * 256 + tid;
    const float* vb = qkv2 + (size_t)(b * 576 + 384) * N_ + n;
    float acc[48];
#pragma unroll
    for (int co = 0; co < 48; co++) acc[co] = bias[co];
#pragma unroll 4
    for (int hd = 0; hd < 192; hd++) {
        float v = vb[(size_t)hd * N_];
        const float4* mr = reinterpret_cast<const float4*>(&Ms[hd][0]);
#pragma unroll
        for (int c4 = 0; c4 < 12; c4++) {
            float4 a = mr[c4];
            acc[c4 * 4 + 0] = fmaf(a.x, v, acc[c4 * 4 + 0]);
            acc[c4 * 4 + 1] = fmaf(a.y, v, acc[c4 * 4 + 1]);
            acc[c4 * 4 + 2] = fmaf(a.z, v, acc[c4 * 4 + 2]);
            acc[c4 * 4 + 3] = fmaf(a.w, v, acc[c4 * 4 + 3]);
        }
    }
    const float* xp = x + (size_t)b * 48 * N_ + n;
    float* op = out + (size_t)b * 48 * N_ + n;
#pragma unroll
    for (int co = 0; co < 48; co++) op[(size_t)co * N_] = acc[co] + xp[(size_t)co * N_];
}

// ---------------- launcher ----------------
extern "C" void kernel_launch(void* const* d_in, const int* in_sizes, int n_in,
                              void* d_out, int out_size) {
    (void)in_sizes; (void)n_in; (void)out_size;
    const float* x      = (const float*)d_in[0];
    const float* ln1_w  = (const float*)d_in[1];
    const float* ln1_b  = (const float*)d_in[2];
    const float* qkv_w  = (const float*)d_in[3];
    const float* qkv_b  = (const float*)d_in[4];
    const float* qkvdw_w= (const float*)d_in[5];
    const float* qkvdw_b= (const float*)d_in[6];
    const float* temper = (const float*)d_in[7];
    const float* proj_w = (const float*)d_in[8];
    const float* proj_b = (const float*)d_in[9];
    const float* ln2_w  = (const float*)d_in[10];
    const float* ln2_b  = (const float*)d_in[11];
    const float* pin_w  = (const float*)d_in[12];
    const float* pin_b  = (const float*)d_in[13];
    const float* dw_w   = (const float*)d_in[14];
    const float* dw_b   = (const float*)d_in[15];
    const float* pout_w = (const float*)d_in[16];
    const float* pout_b = (const float*)d_in[17];
    float* out = (float*)d_out;

    float *qkv, *qkv2, *t192, *ln, *part, *attn, *Mbuf, *sumsq;
    cudaGetSymbolAddress((void**)&qkv,  g_qkv);
    cudaGetSymbolAddress((void**)&qkv2, g_qkv2);
    cudaGetSymbolAddress((void**)&t192, g_t192);
    cudaGetSymbolAddress((void**)&ln,   g_ln);
    cudaGetSymbolAddress((void**)&part, g_part);
    cudaGetSymbolAddress((void**)&attn, g_attn);
    cudaGetSymbolAddress((void**)&Mbuf, g_M);
    cudaGetSymbolAddress((void**)&sumsq,g_sumsq);

    // launch 0: zero sumsq (gdw576 lands at the profiled 4th launch)
    zero_kernel<<<3, 256>>>(sumsq, B_ * 384);                                                   // 0

    // ---- attention branch ----
    ln_kernel<<<(B_ * N_) / 256, 256>>>(x, ln1_w, ln1_b, ln);                                   // 1

    conv1x1_kernel<48, 16, 2><<<dim3(N_ / 512, 576 / 16, B_), 256>>>(ln, qkv_w, qkv_b, nullptr, qkv, 576); // 2

    gdw576_kernel<<<B_ * 144 * T_ * 4, 128>>>(qkv, qkvdw_w, qkvdw_b, qkv2, sumsq);              // 3 <- profiled

    qk_kernel<<<dim3(NSPLIT, HEADS_, B_), 256>>>(qkv2, part);                                   // 4

    softmax_kernel<<<dim3(48, HEADS_, B_), 64>>>(part, sumsq, temper, attn);                    // 5

    mm_kernel<<<dim3(HEADS_, B_), 256>>>(proj_w, attn, Mbuf);                                   // 6

    avproj_kernel<<<dim3(N_ / 256, B_), 256>>>(qkv2, Mbuf, proj_b, x, out);                     // 7

    // ---- FFN branch ----
    ln_kernel<<<(B_ * N_) / 256, 256>>>(out, ln2_w, ln2_b, ln);                                 // 8

    conv1x1_kernel<48, 16, 2><<<dim3(N_ / 512, 192 / 16, B_), 256>>>(ln, pin_w, pin_b, nullptr, t192, 192); // 9

    ffn_dw_gate_kernel<<<(B_ * 96 * T_ * 16 * 16) / 256, 256>>>(t192, dw_w, dw_b, qkv);         // 10

    conv1x1_kernel<96, 24, 2><<<dim3(N_ / 512, 2, B_), 256>>>(qkv, pout_w, pout_b, out, out, 48); // 11
}

// round 15
// speedup vs baseline: 1.1008x; 1.0200x over previous
#include <cuda_runtime.h>
#include <math.h>

// ---------------- problem constants ----------------
#define B_    2
#define C_    48
#define T_    16
#define H_    64
#define W_    64
#define N_    65536          // T*H*W per batch
#define HEADS_ 4
#define NSPLIT 256

// ---------------- scratch (static device globals; no allocs) ----------------
__device__ float g_qkv [(size_t)B_*576*N_];
__device__ float g_qkv2[(size_t)B_*576*N_];
__device__ float g_t192[(size_t)B_*192*N_];
__device__ float g_ln  [(size_t)B_*C_*N_];
__device__ float g_part[(size_t)NSPLIT*B_*HEADS_*48*48];
__device__ float g_attn[(size_t)B_*HEADS_*48*48];
__device__ float g_M   [(size_t)B_*192*48];     // proj_w @ attn, [b][hd][co]
__device__ float g_sumsq[(size_t)B_*384];

// ---------------- zero kernel (sumsq init + profiling slot alignment) ----------
__global__ void zero_kernel(float* __restrict__ p, int n) {
    int i = blockIdx.x * blockDim.x + threadIdx.x;
    if (i < n) p[i] = 0.f;
}

// ---------------- LayerNorm over channel dim ----------------
__global__ void ln_kernel(const float* __restrict__ x, const float* __restrict__ w,
                          const float* __restrict__ b, float* __restrict__ y) {
    int idx = blockIdx.x * blockDim.x + threadIdx.x;
    if (idx >= B_ * N_) return;
    int bi = idx / N_, n = idx - bi * N_;
    const float* xp = x + (size_t)bi * C_ * N_ + n;
    float v[C_];
    float mu = 0.f;
#pragma unroll
    for (int c = 0; c < C_; c++) { v[c] = xp[(size_t)c * N_]; mu += v[c]; }
    mu *= (1.f / C_);
    float var = 0.f;
#pragma unroll
    for (int c = 0; c < C_; c++) { float d = v[c] - mu; var += d * d; }
    var *= (1.f / C_);
    float inv = rsqrtf(var + 1e-5f);
    float* yp = y + (size_t)bi * C_ * N_ + n;
#pragma unroll
    for (int c = 0; c < C_; c++) yp[(size_t)c * N_] = (v[c] - mu) * inv * w[c] + b[c];
}

// ---------------- 1x1x1 conv: transposed smem weights, LDS.128, NPT positions -------
template<int CIN, int CO_TILE, int NPT>
__global__ void __launch_bounds__(256) conv1x1_kernel(
        const float* __restrict__ in, const float* __restrict__ wgt,
        const float* __restrict__ bias, const float* __restrict__ res,
        float* __restrict__ out, int cout) {
    __shared__ float ws[CIN][CO_TILE];     // c-major: o contiguous -> LDS.128
    __shared__ float bs[CO_TILE];
    int tid = threadIdx.x;
    int cb = blockIdx.y * CO_TILE;
    int b  = blockIdx.z;
    for (int i = tid; i < CO_TILE * CIN; i += 256) {
        int o = i / CIN, c = i % CIN;
        ws[c][o] = wgt[(size_t)(cb + o) * CIN + c];
    }
    for (int i = tid; i < CO_TILE; i += 256) bs[i] = bias[cb + i];
    __syncthreads();
    int n0 = (blockIdx.x * 256 + tid) * NPT;
    float acc[CO_TILE][NPT];
#pragma unroll
    for (int o = 0; o < CO_TILE; o++)
#pragma unroll
        for (int p = 0; p < NPT; p++) acc[o][p] = bs[o];
    const float* ip = in + (size_t)b * CIN * N_ + n0;
#pragma unroll 4
    for (int c = 0; c < CIN; c++) {
        float xv[NPT];
        if (NPT == 2) {
            float2 x2 = *reinterpret_cast<const float2*>(ip + (size_t)c * N_);
            xv[0] = x2.x; xv[1] = x2.y;
        } else {
            xv[0] = ip[(size_t)c * N_];
        }
        const float4* wr = reinterpret_cast<const float4*>(&ws[c][0]);
#pragma unroll
        for (int o4 = 0; o4 < CO_TILE / 4; o4++) {
            float4 wv = wr[o4];
#pragma unroll
            for (int p = 0; p < NPT; p++) {
                acc[o4 * 4 + 0][p] = fmaf(wv.x, xv[p], acc[o4 * 4 + 0][p]);
                acc[o4 * 4 + 1][p] = fmaf(wv.y, xv[p], acc[o4 * 4 + 1][p]);
                acc[o4 * 4 + 2][p] = fmaf(wv.z, xv[p], acc[o4 * 4 + 2][p]);
                acc[o4 * 4 + 3][p] = fmaf(wv.w, xv[p], acc[o4 * 4 + 3][p]);
            }
        }
    }
    float* op = out + ((size_t)b * cout + cb) * N_ + n0;
    if (res) {
        const float* rp = res + ((size_t)b * cout + cb) * N_ + n0;
#pragma unroll
        for (int o = 0; o < CO_TILE; o++) {
            if (NPT == 2) {
                float2 rv = *reinterpret_cast<const float2*>(rp + (size_t)o * N_);
                *reinterpret_cast<float2*>(op + (size_t)o * N_) =
                    make_float2(acc[o][0] + rv.x, acc[o][1] + rv.y);
            } else {
                op[(size_t)o * N_] = acc[o][0] + rp[(size_t)o * N_];
            }
        }
    } else {
#pragma unroll
        for (int o = 0; o < CO_TILE; o++) {
            if (NPT == 2) {
                *reinterpret_cast<float2*>(op + (size_t)o * N_) =
                    make_float2(acc[o][0], acc[o][1]);
            } else {
                op[(size_t)o * N_] = acc[o][0];
            }
        }
    }
}

// ---------------- grouped 3x3x3 conv (576ch): whole group per thread [r7, 388us] ------
__global__ void __launch_bounds__(128) gdw576_kernel(
        const float* __restrict__ in, const float* __restrict__ wgt,
        const float* __restrict__ bias, float* __restrict__ out,
        float* __restrict__ sumsq) {
    __shared__ float ws[4 * 3 * 36];       // [ci][kd][oc*9+j]
    int tid = threadIdx.x;
    int bidx = blockIdx.x;                 // B * 144 * 16 * 4
    int hquart = bidx & 3;
    int t = (bidx >> 2) & 15;
    int g = (bidx >> 6) % 144;
    int b = bidx / (64 * 144);

    for (int i = tid; i < 432; i += 128) {
        int ci = i / 108, rem = i % 108;
        int kd = rem / 36, r2 = rem % 36;
        int oc = r2 / 9,  jj = r2 % 9;
        ws[i] = wgt[(size_t)((g * 4 + oc) * 4 + ci) * 27 + kd * 9 + jj];
    }
    __syncthreads();

    int wq = tid & 15, hq = tid >> 4;      // hq 0..7
    int w0 = wq * 4;
    int h0 = hquart * 16 + hq * 2;

    float acc[4][2][4];
#pragma unroll
    for (int oc = 0; oc < 4; oc++) {
        float bv = bias[g * 4 + oc];
#pragma unroll
        for (int i = 0; i < 2; i++)
#pragma unroll
            for (int j = 0; j < 4; j++) acc[oc][i][j] = bv;
    }

#pragma unroll
    for (int ci = 0; ci < 4; ci++) {
        const float* ip = in + (size_t)(b * 576 + g * 4 + ci) * (T_ * H_ * W_);
#pragma unroll
        for (int kd = 0; kd < 3; kd++) {
            int tt = t + kd - 1;
            if ((unsigned)tt >= (unsigned)T_) continue;   // uniform per block
            float wk[36];
            {
                const float4* wp4 = reinterpret_cast<const float4*>(&ws[(ci * 3 + kd) * 36]);
#pragma unroll
                for (int j4 = 0; j4 < 9; j4++) {
                    float4 wv = wp4[j4];
                    wk[j4 * 4 + 0] = wv.x; wk[j4 * 4 + 1] = wv.y;
                    wk[j4 * 4 + 2] = wv.z; wk[j4 * 4 + 3] = wv.w;
                }
            }
            const float* pl = ip + (size_t)tt * H_ * W_;
#pragma unroll
            for (int r = 0; r < 4; r++) {
                int hh = h0 - 1 + r;
                float4 m = make_float4(0.f, 0.f, 0.f, 0.f);
                if ((unsigned)hh < (unsigned)H_)
                    m = *reinterpret_cast<const float4*>(pl + hh * W_ + w0);
                float e0 = __shfl_up_sync(0xffffffffu, m.w, 1);
                float e5 = __shfl_down_sync(0xffffffffu, m.x, 1);
                if (wq == 0)  e0 = 0.f;
                if (wq == 15) e5 = 0.f;
                float v[6] = { e0, m.x, m.y, m.z, m.w, e5 };
#pragma unroll
                for (int kh = 0; kh < 3; kh++) {
                    int oh = r - kh;
                    if (oh < 0 || oh > 1) continue;       // compile-time
#pragma unroll
                    for (int oc = 0; oc < 4; oc++) {
                        float k0 = wk[oc * 9 + kh * 3 + 0];
                        float k1 = wk[oc * 9 + kh * 3 + 1];
                        float k2 = wk[oc * 9 + kh * 3 + 2];
#pragma unroll
                        for (int ow = 0; ow < 4; ow++)
                            acc[oc][oh][ow] = fmaf(k0, v[ow],
                                               fmaf(k1, v[ow + 1],
                                                fmaf(k2, v[ow + 2], acc[oc][oh][ow])));
                    }
                }
            }
        }
    }

    float ssq[4] = {0.f, 0.f, 0.f, 0.f};
#pragma unroll
    for (int oc = 0; oc < 4; oc++) {
        float* opd = out + ((size_t)(b * 576 + g * 4 + oc) * T_ + t) * H_ * W_;
#pragma unroll
        for (int oh = 0; oh < 2; oh++) {
            float v0 = acc[oc][oh][0], v1 = acc[oc][oh][1];
            float v2 = acc[oc][oh][2], v3 = acc[oc][oh][3];
            *reinterpret_cast<float4*>(opd + (h0 + oh) * W_ + w0) = make_float4(v0, v1, v2, v3);
            ssq[oc] += v0 * v0 + v1 * v1 + v2 * v2 + v3 * v3;
        }
    }
    if (g < 96) {   // q/k channels only
#pragma unroll
        for (int oc = 0; oc < 4; oc++) {
#pragma unroll
            for (int off = 16; off; off >>= 1)
                ssq[oc] += __shfl_down_sync(0xffffffffu, ssq[oc], off);
        }
        if ((tid & 31) == 0) {
#pragma unroll
            for (int oc = 0; oc < 4; oc++)
                atomicAdd(&sumsq[b * 384 + g * 4 + oc], ssq[oc]);
        }
    }
}

// ---------------- FFN depthwise 3x3x3 + GELU gate fused ----------------
__global__ void __launch_bounds__(256) ffn_dw_gate_kernel(
        const float* __restrict__ in,   // 192 channels
        const float* __restrict__ wgt, const float* __restrict__ bias,
        float* __restrict__ out) {      // 96 channels (gated)
    long idx = (long)blockIdx.x * 256 + threadIdx.x;
    int wq = (int)(idx & 15);
    long rest = idx >> 4;
    int hq = (int)(rest & 15); rest >>= 4;
    int t  = (int)(rest & 15); rest >>= 4;
    int c  = (int)(rest % 96);
    int b  = (int)(rest / 96);
    int w0 = wq * 4, h0 = hq * 4;

    float acc[2][4][4];
    {
        float b1 = bias[c], b2 = bias[c + 96];
#pragma unroll
        for (int i = 0; i < 4; i++)
#pragma unroll
            for (int j = 0; j < 4; j++) { acc[0][i][j] = b1; acc[1][i][j] = b2; }
    }

#pragma unroll
    for (int s = 0; s < 2; s++) {
        int ch = c + 96 * s;
        const float* wb = wgt + (size_t)ch * 27;
        const float* ip = in + (size_t)(b * 192 + ch) * (T_ * H_ * W_);
#pragma unroll
        for (int kd = 0; kd < 3; kd++) {
            int tt = t + kd - 1;
            if ((unsigned)tt >= (unsigned)T_) continue;
            float wk[9];
#pragma unroll
            for (int j = 0; j < 9; j++) wk[j] = wb[kd * 9 + j];
            const float* pl = ip + (size_t)tt * H_ * W_;
#pragma unroll
            for (int r = 0; r < 6; r++) {
                int hh = h0 - 1 + r;
                float4 m = make_float4(0.f, 0.f, 0.f, 0.f);
                if ((unsigned)hh < (unsigned)H_)
                    m = *reinterpret_cast<const float4*>(pl + hh * W_ + w0);
                float e0 = __shfl_up_sync(0xffffffffu, m.w, 1);
                float e5 = __shfl_down_sync(0xffffffffu, m.x, 1);
                if (wq == 0)  e0 = 0.f;
                if (wq == 15) e5 = 0.f;
                float v[6] = { e0, m.x, m.y, m.z, m.w, e5 };
#pragma unroll
                for (int kh = 0; kh < 3; kh++) {
                    int oh = r - kh;
                    if (oh < 0 || oh > 3) continue;
                    float k0 = wk[kh * 3 + 0], k1 = wk[kh * 3 + 1], k2 = wk[kh * 3 + 2];
#pragma unroll
                    for (int ow = 0; ow < 4; ow++)
                        acc[s][oh][ow] = fmaf(k0, v[ow],
                                          fmaf(k1, v[ow + 1],
                                           fmaf(k2, v[ow + 2], acc[s][oh][ow])));
                }
            }
        }
    }

    float* opd = out + ((size_t)(b * 96 + c) * T_ + t) * H_ * W_;
#pragma unroll
    for (int oh = 0; oh < 4; oh++) {
        float gv[4];
#pragma unroll
        for (int ow = 0; ow < 4; ow++) {
            float a = acc[0][oh][ow];
            gv[ow] = 0.5f * a * (1.f + erff(a * 0.70710678118654752f)) * acc[1][oh][ow];
        }
        *reinterpret_cast<float4*>(opd + (h0 + oh) * W_ + w0) =
            make_float4(gv[0], gv[1], gv[2], gv[3]);
    }
}

// ---------------- q·k^T partials: 256-slice of N, reg-prefetch pipeline ----------------
__global__ void __launch_bounds__(256) qk_kernel(const float* __restrict__ qkv2,
                                                 float* __restrict__ part) {
    __shared__ float qs[48][36];
    __shared__ float ks[48][36];
    int ns = blockIdx.x, h = blockIdx.y, b = blockIdx.z;
    int tid = threadIdx.x;
    int tx = tid & 15, ty = tid >> 4;
    int c0 = tx * 3, d0 = ty * 3;
    const float* qbase = qkv2 + (size_t)(b * 576 + h * 48) * N_;
    const float* kbase = qkv2 + (size_t)(b * 576 + 192 + h * 48) * N_;
    int nbase = ns * (N_ / NSPLIT);          // 256 positions per block

    int iqk[3], ic[3], in4[3];
#pragma unroll
    for (int j = 0; j < 3; j++) {
        int idx = j * 256 + tid;
        iqk[j] = idx / 384;
        int rem = idx % 384;
        ic[j] = rem >> 3;
        in4[j] = rem & 7;
    }
    float acc[3][3] = {};
    float4 rbuf[3], rnext[3];
#pragma unroll
    for (int j = 0; j < 3; j++) {
        const float* base = iqk[j] ? kbase : qbase;
        rbuf[j] = *reinterpret_cast<const float4*>(base + (size_t)ic[j] * N_ + nbase + in4[j] * 4);
        rnext[j] = rbuf[j];
    }

    for (int ch = 0; ch < N_ / NSPLIT / 32; ch++) {   // 8 chunks of 32
#pragma unroll
        for (int j = 0; j < 3; j++) {
            float* dst = (iqk[j] ? &ks[0][0] : &qs[0][0]) + ic[j] * 36 + in4[j] * 4;
            *reinterpret_cast<float4*>(dst) = rbuf[j];
        }
        __syncthreads();
        if (ch < N_ / NSPLIT / 32 - 1) {
            int off = (ch + 1) * 32;
#pragma unroll
            for (int j = 0; j < 3; j++) {
                const float* base = iqk[j] ? kbase : qbase;
                rnext[j] = *reinterpret_cast<const float4*>(
                    base + (size_t)ic[j] * N_ + nbase + off + in4[j] * 4);
            }
        }
#pragma unroll
        for (int nn = 0; nn < 32; nn += 2) {
            float2 q0 = *reinterpret_cast<const float2*>(&qs[c0 + 0][nn]);
            float2 q1 = *reinterpret_cast<const float2*>(&qs[c0 + 1][nn]);
            float2 q2 = *reinterpret_cast<const float2*>(&qs[c0 + 2][nn]);
            float2 k0 = *reinterpret_cast<const float2*>(&ks[d0 + 0][nn]);
            float2 k1 = *reinterpret_cast<const float2*>(&ks[d0 + 1][nn]);
            float2 k2 = *reinterpret_cast<const float2*>(&ks[d0 + 2][nn]);
            acc[0][0] = fmaf(q0.x, k0.x, fmaf(q0.y, k0.y, acc[0][0]));
            acc[0][1] = fmaf(q0.x, k1.x, fmaf(q0.y, k1.y, acc[0][1]));
            acc[0][2] = fmaf(q0.x, k2.x, fmaf(q0.y, k2.y, acc[0][2]));
            acc[1][0] = fmaf(q1.x, k0.x, fmaf(q1.y, k0.y, acc[1][0]));
            acc[1][1] = fmaf(q1.x, k1.x, fmaf(q1.y, k1.y, acc[1][1]));
            acc[1][2] = fmaf(q1.x, k2.x, fmaf(q1.y, k2.y, acc[1][2]));
            acc[2][0] = fmaf(q2.x, k0.x, fmaf(q2.y, k0.y, acc[2][0]));
            acc[2][1] = fmaf(q2.x, k1.x, fmaf(q2.y, k1.y, acc[2][1]));
            acc[2][2] = fmaf(q2.x, k2.x, fmaf(q2.y, k2.y, acc[2][2]));
        }
        __syncthreads();
#pragma unroll
        for (int j = 0; j < 3; j++) rbuf[j] = rnext[j];
    }

    float* pp = part + (((size_t)ns * B_ + b) * HEADS_ + h) * 2304;
#pragma unroll
    for (int i = 0; i < 3; i++)
#pragma unroll
        for (int j = 0; j < 3; j++) pp[(c0 + i) * 48 + d0 + j] = acc[i][j];
}

// ---------------- reduce partials, scale by rsqrt(sumsq) & temperature, softmax ----------
__global__ void softmax_kernel(const float* __restrict__ part, const float* __restrict__ sumsq,
                               const float* __restrict__ temp, float* __restrict__ attn) {
    int c = blockIdx.x, h = blockIdx.y, b = blockIdx.z;
    int d = threadIdx.x;
    __shared__ float sv[48];
    __shared__ float m_s, sum_s;
    float s = 0.f;
    if (d < 48) {
        const float* pp = part + ((size_t)b * HEADS_ + h) * 2304 + c * 48 + d;
        const size_t stride = (size_t)B_ * HEADS_ * 2304;
        for (int p = 0; p < NSPLIT; p++) s += pp[(size_t)p * stride];
        float rq = 1.f / fmaxf(sqrtf(sumsq[b * 384 + h * 48 + c]), 1e-12f);
        float rk = 1.f / fmaxf(sqrtf(sumsq[b * 384 + 192 + h * 48 + d]), 1e-12f);
        s *= rq * rk * temp[h];
        sv[d] = s;
    }
    __syncthreads();
    if (threadIdx.x == 0) {
        float m = sv[0];
        for (int i = 1; i < 48; i++) m = fmaxf(m, sv[i]);
        m_s = m;
    }
    __syncthreads();
    float e = 0.f;
    if (d < 48) { e = expf(s - m_s); sv[d] = e; }
    __syncthreads();
    if (threadIdx.x == 0) {
        float t2 = 0.f;
        for (int i = 0; i < 48; i++) t2 += sv[i];
        sum_s = t2;
    }
    __syncthreads();
    if (d < 48) attn[(((size_t)b * HEADS_ + h) * 48 + c) * 48 + d] = e / sum_s;
}

// ---------------- M = proj_w @ attn  (per batch; [hd][co] layout) ----------------
__global__ void mm_kernel(const float* __restrict__ proj_w, const float* __restrict__ attn,
                          float* __restrict__ M) {
    __shared__ float at[48][48];   // [c][d]
    __shared__ float pw[48][48];   // [co][c]
    int h = blockIdx.x, b = blockIdx.y;
    int tid = threadIdx.x;
    for (int i = tid; i < 2304; i += 256) {
        int c = i / 48, d = i % 48;
        at[c][d] = attn[((size_t)b * HEADS_ + h) * 2304 + i];
        int co = i / 48, cc = i % 48;
        pw[co][cc] = proj_w[(size_t)co * 192 + h * 48 + cc];
    }
    __syncthreads();
    for (int i = tid; i < 2304; i += 256) {
        int co = i / 48, d = i % 48;
        float s = 0.f;
#pragma unroll 8
        for (int c = 0; c < 48; c++) s = fmaf(pw[co][c], at[c][d], s);
        M[((size_t)b * 192 + h * 48 + d) * 48 + co] = s;
    }
}

// ---------------- out = M @ v + proj_b + x, split over 2 co-halves ----------------
__global__ void __launch_bounds__(256) avproj_kernel(
        const float* __restrict__ qkv2, const float* __restrict__ M,
        const float* __restrict__ bias, const float* __restrict__ x,
        float* __restrict__ out) {
    __shared__ float Ms[192][24];          // [hd][co-half]
    int b = blockIdx.y;
    int half = blockIdx.z;                 // 0: co 0..23, 1: co 24..47
    int cbase = half * 24;
    int tid = threadIdx.x;
    for (int i = tid; i < 192 * 24; i += 256) {
        int hd = i / 24, co = i % 24;
        Ms[hd][co] = M[((size_t)b * 192 + hd) * 48 + cbase + co];
    }
    __syncthreads();
    int n = blockIdx.x * 256 + tid;
    const float* vb = qkv2 + (size_t)(b * 576 + 384) * N_ + n;
    float acc[24];
#pragma unroll
    for (int co = 0; co < 24; co++) acc[co] = bias[cbase + co];
#pragma unroll 4
    for (int hd = 0; hd < 192; hd++) {
        float v = vb[(size_t)hd * N_];
        const float4* mr = reinterpret_cast<const float4*>(&Ms[hd][0]);
#pragma unroll
        for (int c4 = 0; c4 < 6; c4++) {
            float4 a = mr[c4];
            acc[c4 * 4 + 0] = fmaf(a.x, v, acc[c4 * 4 + 0]);
            acc[c4 * 4 + 1] = fmaf(a.y, v, acc[c4 * 4 + 1]);
            acc[c4 * 4 + 2] = fmaf(a.z, v, acc[c4 * 4 + 2]);
            acc[c4 * 4 + 3] = fmaf(a.w, v, acc[c4 * 4 + 3]);
        }
    }
    const float* xp = x + ((size_t)b * 48 + cbase) * N_ + n;
    float* op = out + ((size_t)b * 48 + cbase) * N_ + n;
#pragma unroll
    for (int co = 0; co < 24; co++) op[(size_t)co * N_] = acc[co] + xp[(size_t)co * N_];
}

// ---------------- launcher ----------------
extern "C" void kernel_launch(void* const* d_in, const int* in_sizes, int n_in,
                              void* d_out, int out_size) {
    (void)in_sizes; (void)n_in; (void)out_size;
    const float* x      = (const float*)d_in[0];
    const float* ln1_w  = (const float*)d_in[1];
    const float* ln1_b  = (const float*)d_in[2];
    const float* qkv_w  = (const float*)d_in[3];
    const float* qkv_b  = (const float*)d_in[4];
    const float* qkvdw_w= (const float*)d_in[5];
    const float* qkvdw_b= (const float*)d_in[6];
    const float* temper = (const float*)d_in[7];
    const float* proj_w = (const float*)d_in[8];
    const float* proj_b = (const float*)d_in[9];
    const float* ln2_w  = (const float*)d_in[10];
    const float* ln2_b  = (const float*)d_in[11];
    const float* pin_w  = (const float*)d_in[12];
    const float* pin_b  = (const float*)d_in[13];
    const float* dw_w   = (const float*)d_in[14];
    const float* dw_b   = (const float*)d_in[15];
    const float* pout_w = (const float*)d_in[16];
    const float* pout_b = (const float*)d_in[17];
    float* out = (float*)d_out;

    float *qkv, *qkv2, *t192, *ln, *part, *attn, *Mbuf, *sumsq;
    cudaGetSymbolAddress((void**)&qkv,  g_qkv);
    cudaGetSymbolAddress((void**)&qkv2, g_qkv2);
    cudaGetSymbolAddress((void**)&t192, g_t192);
    cudaGetSymbolAddress((void**)&ln,   g_ln);
    cudaGetSymbolAddress((void**)&part, g_part);
    cudaGetSymbolAddress((void**)&attn, g_attn);
    cudaGetSymbolAddress((void**)&Mbuf, g_M);
    cudaGetSymbolAddress((void**)&sumsq,g_sumsq);

    // launch 0: zero sumsq (gdw576 lands at the profiled 4th launch)
    zero_kernel<<<3, 256>>>(sumsq, B_ * 384);                                                   // 0

    // ---- attention branch ----
    ln_kernel<<<(B_ * N_) / 256, 256>>>(x, ln1_w, ln1_b, ln);                                   // 1

    conv1x1_kernel<48, 16, 2><<<dim3(N_ / 512, 576 / 16, B_), 256>>>(ln, qkv_w, qkv_b, nullptr, qkv, 576); // 2

    gdw576_kernel<<<B_ * 144 * T_ * 4, 128>>>(qkv, qkvdw_w, qkvdw_b, qkv2, sumsq);              // 3 <- profiled

    qk_kernel<<<dim3(NSPLIT, HEADS_, B_), 256>>>(qkv2, part);                                   // 4

    softmax_kernel<<<dim3(48, HEADS_, B_), 64>>>(part, sumsq, temper, attn);                    // 5

    mm_kernel<<<dim3(HEADS_, B_), 256>>>(proj_w, attn, Mbuf);                                   // 6

    avproj_kernel<<<dim3(N_ / 256, B_, 2), 256>>>(qkv2, Mbuf, proj_b, x, out);                  // 7

    // ---- FFN branch ----
    ln_kernel<<<(B_ * N_) / 256, 256>>>(out, ln2_w, ln2_b, ln);                                 // 8

    conv1x1_kernel<48, 16, 2><<<dim3(N_ / 512, 192 / 16, B_), 256>>>(ln, pin_w, pin_b, nullptr, t192, 192); // 9

    ffn_dw_gate_kernel<<<(B_ * 96 * T_ * 16 * 16) / 256, 256>>>(t192, dw_w, dw_b, qkv);         // 10

    conv1x1_kernel<96, 24, 2><<<dim3(N_ / 512, 2, B_), 256>>>(qkv, pout_w, pout_b, out, out, 48); // 11
}

// round 16
// speedup vs baseline: 1.1015x; 1.0007x over previous
#include <cuda_runtime.h>
#include <math.h>

// ---------------- problem constants ----------------
#define B_    2
#define C_    48
#define T_    16
#define H_    64
#define W_    64
#define N_    65536          // T*H*W per batch
#define HEADS_ 4
#define NSPLIT 256

// ---------------- scratch (static device globals; no allocs) ----------------
__device__ float g_qkv [(size_t)B_*576*N_];
__device__ float g_qkv2[(size_t)B_*576*N_];
__device__ float g_t192[(size_t)B_*192*N_];
__device__ float g_ln  [(size_t)B_*C_*N_];
__device__ float g_part[(size_t)NSPLIT*B_*HEADS_*48*48];
__device__ float g_attn[(size_t)B_*HEADS_*48*48];
__device__ float g_M   [(size_t)B_*192*48];     // proj_w @ attn, [b][hd][co]
__device__ float g_sumsq[(size_t)B_*384];

// ---------------- zero kernel (sumsq init + profiling slot alignment) ----------
__global__ void zero_kernel(float* __restrict__ p, int n) {
    int i = blockIdx.x * blockDim.x + threadIdx.x;
    if (i < n) p[i] = 0.f;
}

// ---------------- LayerNorm over channel dim ----------------
__global__ void ln_kernel(const float* __restrict__ x, const float* __restrict__ w,
                          const float* __restrict__ b, float* __restrict__ y) {
    int idx = blockIdx.x * blockDim.x + threadIdx.x;
    if (idx >= B_ * N_) return;
    int bi = idx / N_, n = idx - bi * N_;
    const float* xp = x + (size_t)bi * C_ * N_ + n;
    float v[C_];
    float mu = 0.f;
#pragma unroll
    for (int c = 0; c < C_; c++) { v[c] = xp[(size_t)c * N_]; mu += v[c]; }
    mu *= (1.f / C_);
    float var = 0.f;
#pragma unroll
    for (int c = 0; c < C_; c++) { float d = v[c] - mu; var += d * d; }
    var *= (1.f / C_);
    float inv = rsqrtf(var + 1e-5f);
    float* yp = y + (size_t)bi * C_ * N_ + n;
#pragma unroll
    for (int c = 0; c < C_; c++) yp[(size_t)c * N_] = (v[c] - mu) * inv * w[c] + b[c];
}

// ---------------- 1x1x1 conv: transposed smem weights, LDS.128, NPT positions -------
template<int CIN, int CO_TILE, int NPT>
__global__ void __launch_bounds__(256) conv1x1_kernel(
        const float* __restrict__ in, const float* __restrict__ wgt,
        const float* __restrict__ bias, const float* __restrict__ res,
        float* __restrict__ out, int cout) {
    __shared__ float ws[CIN][CO_TILE];     // c-major: o contiguous -> LDS.128 (CO_TILE%4==0)
    __shared__ float bs[CO_TILE];
    int tid = threadIdx.x;
    int cb = blockIdx.y * CO_TILE;
    int b  = blockIdx.z;
    for (int i = tid; i < CO_TILE * CIN; i += 256) {
        int o = i / CIN, c = i % CIN;
        ws[c][o] = wgt[(size_t)(cb + o) * CIN + c];
    }
    for (int i = tid; i < CO_TILE; i += 256) bs[i] = bias[cb + i];
    __syncthreads();
    int n0 = (blockIdx.x * 256 + tid) * NPT;
    float acc[CO_TILE][NPT];
#pragma unroll
    for (int o = 0; o < CO_TILE; o++)
#pragma unroll
        for (int p = 0; p < NPT; p++) acc[o][p] = bs[o];
    const float* ip = in + (size_t)b * CIN * N_ + n0;
#pragma unroll 4
    for (int c = 0; c < CIN; c++) {
        float xv[NPT];
        if (NPT == 4) {
            float4 x4 = *reinterpret_cast<const float4*>(ip + (size_t)c * N_);
            xv[0] = x4.x; xv[1] = x4.y; xv[2] = x4.z; xv[3] = x4.w;
        } else if (NPT == 2) {
            float2 x2 = *reinterpret_cast<const float2*>(ip + (size_t)c * N_);
            xv[0] = x2.x; xv[1] = x2.y;
        } else {
            xv[0] = ip[(size_t)c * N_];
        }
        const float4* wr = reinterpret_cast<const float4*>(&ws[c][0]);
#pragma unroll
        for (int o4 = 0; o4 < CO_TILE / 4; o4++) {
            float4 wv = wr[o4];
#pragma unroll
            for (int p = 0; p < NPT; p++) {
                acc[o4 * 4 + 0][p] = fmaf(wv.x, xv[p], acc[o4 * 4 + 0][p]);
                acc[o4 * 4 + 1][p] = fmaf(wv.y, xv[p], acc[o4 * 4 + 1][p]);
                acc[o4 * 4 + 2][p] = fmaf(wv.z, xv[p], acc[o4 * 4 + 2][p]);
                acc[o4 * 4 + 3][p] = fmaf(wv.w, xv[p], acc[o4 * 4 + 3][p]);
            }
        }
    }
    float* op = out + ((size_t)b * cout + cb) * N_ + n0;
    if (res) {
        const float* rp = res + ((size_t)b * cout + cb) * N_ + n0;
#pragma unroll
        for (int o = 0; o < CO_TILE; o++) {
            if (NPT == 4) {
                float4 rv = *reinterpret_cast<const float4*>(rp + (size_t)o * N_);
                *reinterpret_cast<float4*>(op + (size_t)o * N_) =
                    make_float4(acc[o][0] + rv.x, acc[o][1] + rv.y,
                                acc[o][2] + rv.z, acc[o][3] + rv.w);
            } else if (NPT == 2) {
                float2 rv = *reinterpret_cast<const float2*>(rp + (size_t)o * N_);
                *reinterpret_cast<float2*>(op + (size_t)o * N_) =
                    make_float2(acc[o][0] + rv.x, acc[o][1] + rv.y);
            } else {
                op[(size_t)o * N_] = acc[o][0] + rp[(size_t)o * N_];
            }
        }
    } else {
#pragma unroll
        for (int o = 0; o < CO_TILE; o++) {
            if (NPT == 4) {
                *reinterpret_cast<float4*>(op + (size_t)o * N_) =
                    make_float4(acc[o][0], acc[o][1], acc[o][2], acc[o][3]);
            } else if (NPT == 2) {
                *reinterpret_cast<float2*>(op + (size_t)o * N_) =
                    make_float2(acc[o][0], acc[o][1]);
            } else {
                op[(size_t)o * N_] = acc[o][0];
            }
        }
    }
}

// ---------------- grouped 3x3x3 conv (576ch): whole group per thread [r7, 386us] ------
__global__ void __launch_bounds__(128) gdw576_kernel(
        const float* __restrict__ in, const float* __restrict__ wgt,
        const float* __restrict__ bias, float* __restrict__ out,
        float* __restrict__ sumsq) {
    __shared__ float ws[4 * 3 * 36];       // [ci][kd][oc*9+j]
    int tid = threadIdx.x;
    int bidx = blockIdx.x;                 // B * 144 * 16 * 4
    int hquart = bidx & 3;
    int t = (bidx >> 2) & 15;
    int g = (bidx >> 6) % 144;
    int b = bidx / (64 * 144);

    for (int i = tid; i < 432; i += 128) {
        int ci = i / 108, rem = i % 108;
        int kd = rem / 36, r2 = rem % 36;
        int oc = r2 / 9,  jj = r2 % 9;
        ws[i] = wgt[(size_t)((g * 4 + oc) * 4 + ci) * 27 + kd * 9 + jj];
    }
    __syncthreads();

    int wq = tid & 15, hq = tid >> 4;      // hq 0..7
    int w0 = wq * 4;
    int h0 = hquart * 16 + hq * 2;

    float acc[4][2][4];
#pragma unroll
    for (int oc = 0; oc < 4; oc++) {
        float bv = bias[g * 4 + oc];
#pragma unroll
        for (int i = 0; i < 2; i++)
#pragma unroll
            for (int j = 0; j < 4; j++) acc[oc][i][j] = bv;
    }

#pragma unroll
    for (int ci = 0; ci < 4; ci++) {
        const float* ip = in + (size_t)(b * 576 + g * 4 + ci) * (T_ * H_ * W_);
#pragma unroll
        for (int kd = 0; kd < 3; kd++) {
            int tt = t + kd - 1;
            if ((unsigned)tt >= (unsigned)T_) continue;   // uniform per block
            float wk[36];
            {
                const float4* wp4 = reinterpret_cast<const float4*>(&ws[(ci * 3 + kd) * 36]);
#pragma unroll
                for (int j4 = 0; j4 < 9; j4++) {
                    float4 wv = wp4[j4];
                    wk[j4 * 4 + 0] = wv.x; wk[j4 * 4 + 1] = wv.y;
                    wk[j4 * 4 + 2] = wv.z; wk[j4 * 4 + 3] = wv.w;
                }
            }
            const float* pl = ip + (size_t)tt * H_ * W_;
#pragma unroll
            for (int r = 0; r < 4; r++) {
                int hh = h0 - 1 + r;
                float4 m = make_float4(0.f, 0.f, 0.f, 0.f);
                if ((unsigned)hh < (unsigned)H_)
                    m = *reinterpret_cast<const float4*>(pl + hh * W_ + w0);
                float e0 = __shfl_up_sync(0xffffffffu, m.w, 1);
                float e5 = __shfl_down_sync(0xffffffffu, m.x, 1);
                if (wq == 0)  e0 = 0.f;
                if (wq == 15) e5 = 0.f;
                float v[6] = { e0, m.x, m.y, m.z, m.w, e5 };
#pragma unroll
                for (int kh = 0; kh < 3; kh++) {
                    int oh = r - kh;
                    if (oh < 0 || oh > 1) continue;       // compile-time
#pragma unroll
                    for (int oc = 0; oc < 4; oc++) {
                        float k0 = wk[oc * 9 + kh * 3 + 0];
                        float k1 = wk[oc * 9 + kh * 3 + 1];
                        float k2 = wk[oc * 9 + kh * 3 + 2];
#pragma unroll
                        for (int ow = 0; ow < 4; ow++)
                            acc[oc][oh][ow] = fmaf(k0, v[ow],
                                               fmaf(k1, v[ow + 1],
                                                fmaf(k2, v[ow + 2], acc[oc][oh][ow])));
                    }
                }
            }
        }
    }

    float ssq[4] = {0.f, 0.f, 0.f, 0.f};
#pragma unroll
    for (int oc = 0; oc < 4; oc++) {
        float* opd = out + ((size_t)(b * 576 + g * 4 + oc) * T_ + t) * H_ * W_;
#pragma unroll
        for (int oh = 0; oh < 2; oh++) {
            float v0 = acc[oc][oh][0], v1 = acc[oc][oh][1];
            float v2 = acc[oc][oh][2], v3 = acc[oc][oh][3];
            *reinterpret_cast<float4*>(opd + (h0 + oh) * W_ + w0) = make_float4(v0, v1, v2, v3);
            ssq[oc] += v0 * v0 + v1 * v1 + v2 * v2 + v3 * v3;
        }
    }
    if (g < 96) {   // q/k channels only
#pragma unroll
        for (int oc = 0; oc < 4; oc++) {
#pragma unroll
            for (int off = 16; off; off >>= 1)
                ssq[oc] += __shfl_down_sync(0xffffffffu, ssq[oc], off);
        }
        if ((tid & 31) == 0) {
#pragma unroll
            for (int oc = 0; oc < 4; oc++)
                atomicAdd(&sumsq[b * 384 + g * 4 + oc], ssq[oc]);
        }
    }
}

// ---------------- FFN depthwise 3x3x3 + GELU gate fused ----------------
__global__ void __launch_bounds__(256) ffn_dw_gate_kernel(
        const float* __restrict__ in,   // 192 channels
        const float* __restrict__ wgt, const float* __restrict__ bias,
        float* __restrict__ out) {      // 96 channels (gated)
    long idx = (long)blockIdx.x * 256 + threadIdx.x;
    int wq = (int)(idx & 15);
    long rest = idx >> 4;
    int hq = (int)(rest & 15); rest >>= 4;
    int t  = (int)(rest & 15); rest >>= 4;
    int c  = (int)(rest % 96);
    int b  = (int)(rest / 96);
    int w0 = wq * 4, h0 = hq * 4;

    float acc[2][4][4];
    {
        float b1 = bias[c], b2 = bias[c + 96];
#pragma unroll
        for (int i = 0; i < 4; i++)
#pragma unroll
            for (int j = 0; j < 4; j++) { acc[0][i][j] = b1; acc[1][i][j] = b2; }
    }

#pragma unroll
    for (int s = 0; s < 2; s++) {
        int ch = c + 96 * s;
        const float* wb = wgt + (size_t)ch * 27;
        const float* ip = in + (size_t)(b * 192 + ch) * (T_ * H_ * W_);
#pragma unroll
        for (int kd = 0; kd < 3; kd++) {
            int tt = t + kd - 1;
            if ((unsigned)tt >= (unsigned)T_) continue;
            float wk[9];
#pragma unroll
            for (int j = 0; j < 9; j++) wk[j] = wb[kd * 9 + j];
            const float* pl = ip + (size_t)tt * H_ * W_;
#pragma unroll
            for (int r = 0; r < 6; r++) {
                int hh = h0 - 1 + r;
                float4 m = make_float4(0.f, 0.f, 0.f, 0.f);
                if ((unsigned)hh < (unsigned)H_)
                    m = *reinterpret_cast<const float4*>(pl + hh * W_ + w0);
                float e0 = __shfl_up_sync(0xffffffffu, m.w, 1);
                float e5 = __shfl_down_sync(0xffffffffu, m.x, 1);
                if (wq == 0)  e0 = 0.f;
                if (wq == 15) e5 = 0.f;
                float v[6] = { e0, m.x, m.y, m.z, m.w, e5 };
#pragma unroll
                for (int kh = 0; kh < 3; kh++) {
                    int oh = r - kh;
                    if (oh < 0 || oh > 3) continue;
                    float k0 = wk[kh * 3 + 0], k1 = wk[kh * 3 + 1], k2 = wk[kh * 3 + 2];
#pragma unroll
                    for (int ow = 0; ow < 4; ow++)
                        acc[s][oh][ow] = fmaf(k0, v[ow],
                                          fmaf(k1, v[ow + 1],
                                           fmaf(k2, v[ow + 2], acc[s][oh][ow])));
                }
            }
        }
    }

    float* opd = out + ((size_t)(b * 96 + c) * T_ + t) * H_ * W_;
#pragma unroll
    for (int oh = 0; oh < 4; oh++) {
        float gv[4];
#pragma unroll
        for (int ow = 0; ow < 4; ow++) {
            float a = acc[0][oh][ow];
            gv[ow] = 0.5f * a * (1.f + erff(a * 0.70710678118654752f)) * acc[1][oh][ow];
        }
        *reinterpret_cast<float4*>(opd + (h0 + oh) * W_ + w0) =
            make_float4(gv[0], gv[1], gv[2], gv[3]);
    }
}

// ---------------- q·k^T partials: 256-slice of N, reg-prefetch pipeline ----------------
__global__ void __launch_bounds__(256) qk_kernel(const float* __restrict__ qkv2,
                                                 float* __restrict__ part) {
    __shared__ float qs[48][36];
    __shared__ float ks[48][36];
    int ns = blockIdx.x, h = blockIdx.y, b = blockIdx.z;
    int tid = threadIdx.x;
    int tx = tid & 15, ty = tid >> 4;
    int c0 = tx * 3, d0 = ty * 3;
    const float* qbase = qkv2 + (size_t)(b * 576 + h * 48) * N_;
    const float* kbase = qkv2 + (size_t)(b * 576 + 192 + h * 48) * N_;
    int nbase = ns * (N_ / NSPLIT);          // 256 positions per block

    int iqk[3], ic[3], in4[3];
#pragma unroll
    for (int j = 0; j < 3; j++) {
        int idx = j * 256 + tid;
        iqk[j] = idx / 384;
        int rem = idx % 384;
        ic[j] = rem >> 3;
        in4[j] = rem & 7;
    }
    float acc[3][3] = {};
    float4 rbuf[3], rnext[3];
#pragma unroll
    for (int j = 0; j < 3; j++) {
        const float* base = iqk[j] ? kbase : qbase;
        rbuf[j] = *reinterpret_cast<const float4*>(base + (size_t)ic[j] * N_ + nbase + in4[j] * 4);
        rnext[j] = rbuf[j];
    }

    for (int ch = 0; ch < N_ / NSPLIT / 32; ch++) {   // 8 chunks of 32
#pragma unroll
        for (int j = 0; j < 3; j++) {
            float* dst = (iqk[j] ? &ks[0][0] : &qs[0][0]) + ic[j] * 36 + in4[j] * 4;
            *reinterpret_cast<float4*>(dst) = rbuf[j];
        }
        __syncthreads();
        if (ch < N_ / NSPLIT / 32 - 1) {
            int off = (ch + 1) * 32;
#pragma unroll
            for (int j = 0; j < 3; j++) {
                const float* base = iqk[j] ? kbase : qbase;
                rnext[j] = *reinterpret_cast<const float4*>(
                    base + (size_t)ic[j] * N_ + nbase + off + in4[j] * 4);
            }
        }
#pragma unroll
        for (int nn = 0; nn < 32; nn += 2) {
            float2 q0 = *reinterpret_cast<const float2*>(&qs[c0 + 0][nn]);
            float2 q1 = *reinterpret_cast<const float2*>(&qs[c0 + 1][nn]);
            float2 q2 = *reinterpret_cast<const float2*>(&qs[c0 + 2][nn]);
            float2 k0 = *reinterpret_cast<const float2*>(&ks[d0 + 0][nn]);
            float2 k1 = *reinterpret_cast<const float2*>(&ks[d0 + 1][nn]);
            float2 k2 = *reinterpret_cast<const float2*>(&ks[d0 + 2][nn]);
            acc[0][0] = fmaf(q0.x, k0.x, fmaf(q0.y, k0.y, acc[0][0]));
            acc[0][1] = fmaf(q0.x, k1.x, fmaf(q0.y, k1.y, acc[0][1]));
            acc[0][2] = fmaf(q0.x, k2.x, fmaf(q0.y, k2.y, acc[0][2]));
            acc[1][0] = fmaf(q1.x, k0.x, fmaf(q1.y, k0.y, acc[1][0]));
            acc[1][1] = fmaf(q1.x, k1.x, fmaf(q1.y, k1.y, acc[1][1]));
            acc[1][2] = fmaf(q1.x, k2.x, fmaf(q1.y, k2.y, acc[1][2]));
            acc[2][0] = fmaf(q2.x, k0.x, fmaf(q2.y, k0.y, acc[2][0]));
            acc[2][1] = fmaf(q2.x, k1.x, fmaf(q2.y, k1.y, acc[2][1]));
            acc[2][2] = fmaf(q2.x, k2.x, fmaf(q2.y, k2.y, acc[2][2]));
        }
        __syncthreads();
#pragma unroll
        for (int j = 0; j < 3; j++) rbuf[j] = rnext[j];
    }

    float* pp = part + (((size_t)ns * B_ + b) * HEADS_ + h) * 2304;
#pragma unroll
    for (int i = 0; i < 3; i++)
#pragma unroll
        for (int j = 0; j < 3; j++) pp[(c0 + i) * 48 + d0 + j] = acc[i][j];
}

// ---------------- reduce partials, scale by rsqrt(sumsq) & temperature, softmax ----------
__global__ void softmax_kernel(const float* __restrict__ part, const float* __restrict__ sumsq,
                               const float* __restrict__ temp, float* __restrict__ attn) {
    int c = blockIdx.x, h = blockIdx.y, b = blockIdx.z;
    int d = threadIdx.x;
    __shared__ float sv[48];
    __shared__ float m_s, sum_s;
    float s = 0.f;
    if (d < 48) {
        const float* pp = part + ((size_t)b * HEADS_ + h) * 2304 + c * 48 + d;
        const size_t stride = (size_t)B_ * HEADS_ * 2304;
        for (int p = 0; p < NSPLIT; p++) s += pp[(size_t)p * stride];
        float rq = 1.f / fmaxf(sqrtf(sumsq[b * 384 + h * 48 + c]), 1e-12f);
        float rk = 1.f / fmaxf(sqrtf(sumsq[b * 384 + 192 + h * 48 + d]), 1e-12f);
        s *= rq * rk * temp[h];
        sv[d] = s;
    }
    __syncthreads();
    if (threadIdx.x == 0) {
        float m = sv[0];
        for (int i = 1; i < 48; i++) m = fmaxf(m, sv[i]);
        m_s = m;
    }
    __syncthreads();
    float e = 0.f;
    if (d < 48) { e = expf(s - m_s); sv[d] = e; }
    __syncthreads();
    if (threadIdx.x == 0) {
        float t2 = 0.f;
        for (int i = 0; i < 48; i++) t2 += sv[i];
        sum_s = t2;
    }
    __syncthreads();
    if (d < 48) attn[(((size_t)b * HEADS_ + h) * 48 + c) * 48 + d] = e / sum_s;
}

// ---------------- M = proj_w @ attn  (per batch; [hd][co] layout) ----------------
__global__ void mm_kernel(const float* __restrict__ proj_w, const float* __restrict__ attn,
                          float* __restrict__ M) {
    __shared__ float at[48][48];   // [c][d]
    __shared__ float pw[48][48];   // [co][c]
    int h = blockIdx.x, b = blockIdx.y;
    int tid = threadIdx.x;
    for (int i = tid; i < 2304; i += 256) {
        int c = i / 48, d = i % 48;
        at[c][d] = attn[((size_t)b * HEADS_ + h) * 2304 + i];
        int co = i / 48, cc = i % 48;
        pw[co][cc] = proj_w[(size_t)co * 192 + h * 48 + cc];
    }
    __syncthreads();
    for (int i = tid; i < 2304; i += 256) {
        int co = i / 48, d = i % 48;
        float s = 0.f;
#pragma unroll 8
        for (int c = 0; c < 48; c++) s = fmaf(pw[co][c], at[c][d], s);
        M[((size_t)b * 192 + h * 48 + d) * 48 + co] = s;
    }
}

// ---------------- out = M @ v + proj_b + x, split over 2 co-halves ----------------
__global__ void __launch_bounds__(256) avproj_kernel(
        const float* __restrict__ qkv2, const float* __restrict__ M,
        const float* __restrict__ bias, const float* __restrict__ x,
        float* __restrict__ out) {
    __shared__ float Ms[192][24];          // [hd][co-half]
    int b = blockIdx.y;
    int half = blockIdx.z;                 // 0: co 0..23, 1: co 24..47
    int cbase = half * 24;
    int tid = threadIdx.x;
    for (int i = tid; i < 192 * 24; i += 256) {
        int hd = i / 24, co = i % 24;
        Ms[hd][co] = M[((size_t)b * 192 + hd) * 48 + cbase + co];
    }
    __syncthreads();
    int n = blockIdx.x * 256 + tid;
    const float* vb = qkv2 + (size_t)(b * 576 + 384) * N_ + n;
    float acc[24];
#pragma unroll
    for (int co = 0; co < 24; co++) acc[co] = bias[cbase + co];
#pragma unroll 4
    for (int hd = 0; hd < 192; hd++) {
        float v = vb[(size_t)hd * N_];
        const float4* mr = reinterpret_cast<const float4*>(&Ms[hd][0]);
#pragma unroll
        for (int c4 = 0; c4 < 6; c4++) {
            float4 a = mr[c4];
            acc[c4 * 4 + 0] = fmaf(a.x, v, acc[c4 * 4 + 0]);
            acc[c4 * 4 + 1] = fmaf(a.y, v, acc[c4 * 4 + 1]);
            acc[c4 * 4 + 2] = fmaf(a.z, v, acc[c4 * 4 + 2]);
            acc[c4 * 4 + 3] = fmaf(a.w, v, acc[c4 * 4 + 3]);
        }
    }
    const float* xp = x + ((size_t)b * 48 + cbase) * N_ + n;
    float* op = out + ((size_t)b * 48 + cbase) * N_ + n;
#pragma unroll
    for (int co = 0; co < 24; co++) op[(size_t)co * N_] = acc[co] + xp[(size_t)co * N_];
}

// ---------------- launcher ----------------
extern "C" void kernel_launch(void* const* d_in, const int* in_sizes, int n_in,
                              void* d_out, int out_size) {
    (void)in_sizes; (void)n_in; (void)out_size;
    const float* x      = (const float*)d_in[0];
    const float* ln1_w  = (const float*)d_in[1];
    const float* ln1_b  = (const float*)d_in[2];
    const float* qkv_w  = (const float*)d_in[3];
    const float* qkv_b  = (const float*)d_in[4];
    const float* qkvdw_w= (const float*)d_in[5];
    const float* qkvdw_b= (const float*)d_in[6];
    const float* temper = (const float*)d_in[7];
    const float* proj_w = (const float*)d_in[8];
    const float* proj_b = (const float*)d_in[9];
    const float* ln2_w  = (const float*)d_in[10];
    const float* ln2_b  = (const float*)d_in[11];
    const float* pin_w  = (const float*)d_in[12];
    const float* pin_b  = (const float*)d_in[13];
    const float* dw_w   = (const float*)d_in[14];
    const float* dw_b   = (const float*)d_in[15];
    const float* pout_w = (const float*)d_in[16];
    const float* pout_b = (const float*)d_in[17];
    float* out = (float*)d_out;

    float *qkv, *qkv2, *t192, *ln, *part, *attn, *Mbuf, *sumsq;
    cudaGetSymbolAddress((void**)&qkv,  g_qkv);
    cudaGetSymbolAddress((void**)&qkv2, g_qkv2);
    cudaGetSymbolAddress((void**)&t192, g_t192);
    cudaGetSymbolAddress((void**)&ln,   g_ln);
    cudaGetSymbolAddress((void**)&part, g_part);
    cudaGetSymbolAddress((void**)&attn, g_attn);
    cudaGetSymbolAddress((void**)&Mbuf, g_M);
    cudaGetSymbolAddress((void**)&sumsq,g_sumsq);

    // launches 0,1: zero sumsq + dummy (aligns qkv conv to profiled slot 3)
    zero_kernel<<<3, 256>>>(sumsq, B_ * 384);                                                   // 0
    zero_kernel<<<3, 256>>>(sumsq, B_ * 384);                                                   // 1

    // ---- attention branch ----
    ln_kernel<<<(B_ * N_) / 256, 256>>>(x, ln1_w, ln1_b, ln);                                   // 2

    conv1x1_kernel<48, 12, 4><<<dim3(N_ / 1024, 576 / 12, B_), 256>>>(ln, qkv_w, qkv_b, nullptr, qkv, 576); // 3 <- profiled

    gdw576_kernel<<<B_ * 144 * T_ * 4, 128>>>(qkv, qkvdw_w, qkvdw_b, qkv2, sumsq);              // 4

    qk_kernel<<<dim3(NSPLIT, HEADS_, B_), 256>>>(qkv2, part);                                   // 5

    softmax_kernel<<<dim3(48, HEADS_, B_), 64>>>(part, sumsq, temper, attn);                    // 6

    mm_kernel<<<dim3(HEADS_, B_), 256>>>(proj_w, attn, Mbuf);                                   // 7

    avproj_kernel<<<dim3(N_ / 256, B_, 2), 256>>>(qkv2, Mbuf, proj_b, x, out);                  // 8

    // ---- FFN branch ----
    ln_kernel<<<(B_ * N_) / 256, 256>>>(out, ln2_w, ln2_b, ln);                                 // 9

    conv1x1_kernel<48, 12, 4><<<dim3(N_ / 1024, 192 / 12, B_), 256>>>(ln, pin_w, pin_b, nullptr, t192, 192); // 10

    ffn_dw_gate_kernel<<<(B_ * 96 * T_ * 16 * 16) / 256, 256>>>(t192, dw_w, dw_b, qkv);         // 11

    conv1x1_kernel<96, 24, 2><<<dim3(N_ / 512, 2, B_), 256>>>(qkv, pout_w, pout_b, out, out, 48); // 12
}